// round 1
// baseline (speedup 1.0000x reference)
#include <cuda_runtime.h>
#include <math.h>

#define Nn 50000
#define Ee 800000
#define NEG 0.2f
#define LNEPS 1e-5f

// ---- scratch (static __device__ arrays: allocation is banned) ----
__device__ float d_feat[Nn * 256];   // GEMM1 output [N, H*F]
__device__ float d_el[Nn * 4];       // left attention logits [N, H]
__device__ float d_er[Nn * 4];       // right attention logits [N, H]
__device__ float d_rst[Nn * 256];    // aggregated features [N, H*F]
__device__ int   d_cnt[Nn];
__device__ int   d_off[Nn + 1];
__device__ int   d_cur[Nn];
__device__ int   d_esrc[Ee];         // src ids sorted by dst (CSR payload)

// ---------------- CSR build ----------------
__global__ void k_zero() {
    int i = blockIdx.x * blockDim.x + threadIdx.x;
    if (i < Nn) d_cnt[i] = 0;
}

__global__ void k_hist(const int* __restrict__ dst) {
    int i = blockIdx.x * blockDim.x + threadIdx.x;
    if (i < Ee) atomicAdd(&d_cnt[dst[i]], 1);
}

__global__ void k_scan() {  // single block, 1024 threads
    __shared__ int ps[1024];
    int t = threadIdx.x;
    const int CH = (Nn + 1023) / 1024;  // 49
    int b = t * CH;
    int e = b + CH; if (e > Nn) e = Nn;
    int s = 0;
    for (int i = b; i < e; i++) s += d_cnt[i];
    ps[t] = s;
    __syncthreads();
    for (int o = 1; o < 1024; o <<= 1) {
        int v = (t >= o) ? ps[t - o] : 0;
        __syncthreads();
        ps[t] += v;
        __syncthreads();
    }
    int run = (t == 0) ? 0 : ps[t - 1];
    for (int i = b; i < e; i++) {
        d_off[i] = run;
        d_cur[i] = run;
        run += d_cnt[i];
    }
    if (t == 1023) d_off[Nn] = ps[1023];
}

__global__ void k_scatter(const int* __restrict__ src, const int* __restrict__ dst) {
    int i = blockIdx.x * blockDim.x + threadIdx.x;
    if (i < Ee) {
        int p = atomicAdd(&d_cur[dst[i]], 1);
        d_esrc[p] = src[i];
    }
}

// ---------------- GEMM1: feat = h @ fc_w  ([N,64] @ [64,256]) ----------------
// Block = 256 threads (8 warps), 64 nodes/block; warp computes 8 nodes x 128 cols per half.
__global__ void k_gemm1(const float* __restrict__ h, const float* __restrict__ fc_w) {
    __shared__ float hs[64 * 64];    // 16 KB
    __shared__ float ws[64 * 128];   // 32 KB (one column-half of fc_w)
    int t = threadIdx.x;
    int lane = t & 31, warp = t >> 5;
    int node0 = blockIdx.x * 64;

    // load h tile (64 nodes x 64 floats) as float4, coalesced
    #pragma unroll
    for (int i = 0; i < 4; i++) {
        int idx = t + i * 256;             // float4 index; 16 float4 per node
        int node = node0 + (idx >> 4);
        float4 v = make_float4(0.f, 0.f, 0.f, 0.f);
        if (node < Nn) v = ((const float4*)h)[node * 16 + (idx & 15)];
        ((float4*)hs)[idx] = v;
    }

    for (int ch = 0; ch < 2; ch++) {
        __syncthreads();  // hs ready (ch=0) / prior compute done (ch=1)
        #pragma unroll
        for (int i = 0; i < 8; i++) {
            int idx = t + i * 256;         // float4 in ws: row=idx>>5, c4=idx&31
            ((float4*)ws)[idx] =
                ((const float4*)fc_w)[(idx >> 5) * 64 + ch * 32 + (idx & 31)];
        }
        __syncthreads();

        float4 acc[8];
        #pragma unroll
        for (int nd = 0; nd < 8; nd++) acc[nd] = make_float4(0.f, 0.f, 0.f, 0.f);

        for (int k = 0; k < 64; k++) {
            float4 w4 = ((float4*)ws)[k * 32 + lane];
            #pragma unroll
            for (int nd = 0; nd < 8; nd++) {
                float hv = hs[(warp * 8 + nd) * 64 + k];
                acc[nd].x += hv * w4.x;
                acc[nd].y += hv * w4.y;
                acc[nd].z += hv * w4.z;
                acc[nd].w += hv * w4.w;
            }
        }
        #pragma unroll
        for (int nd = 0; nd < 8; nd++) {
            int node = node0 + warp * 8 + nd;
            if (node < Nn)
                ((float4*)d_feat)[node * 64 + ch * 32 + lane] = acc[nd];
        }
    }
}

// ---------------- el/er: per-node per-head dot with attn vectors ----------------
// One warp per node. Lane l owns cols [4l..4l+3] (head l>>4) and [128+4l..] (head l>>4 + 2).
__global__ void k_elr(const float* __restrict__ attn_l, const float* __restrict__ attn_r) {
    int gw = (blockIdx.x * blockDim.x + threadIdx.x) >> 5;
    int lane = threadIdx.x & 31;
    if (gw >= Nn) return;
    int n = gw;
    int hA = lane >> 4;

    float4 fa = ((const float4*)d_feat)[n * 64 + lane];
    float4 fb = ((const float4*)d_feat)[n * 64 + 32 + lane];
    float4 ala = ((const float4*)attn_l)[hA * 16 + (lane & 15)];
    float4 alb = ((const float4*)attn_l)[(hA + 2) * 16 + (lane & 15)];
    float4 ara = ((const float4*)attn_r)[hA * 16 + (lane & 15)];
    float4 arb = ((const float4*)attn_r)[(hA + 2) * 16 + (lane & 15)];

    float pla = fa.x * ala.x + fa.y * ala.y + fa.z * ala.z + fa.w * ala.w;
    float plb = fb.x * alb.x + fb.y * alb.y + fb.z * alb.z + fb.w * alb.w;
    float pra = fa.x * ara.x + fa.y * ara.y + fa.z * ara.z + fa.w * ara.w;
    float prb = fb.x * arb.x + fb.y * arb.y + fb.z * arb.z + fb.w * arb.w;

    #pragma unroll
    for (int o = 8; o > 0; o >>= 1) {   // reduce within 16-lane half-warps
        pla += __shfl_xor_sync(0xffffffffu, pla, o);
        plb += __shfl_xor_sync(0xffffffffu, plb, o);
        pra += __shfl_xor_sync(0xffffffffu, pra, o);
        prb += __shfl_xor_sync(0xffffffffu, prb, o);
    }
    if ((lane & 15) == 0) {
        d_el[n * 4 + hA]     = pla;
        d_el[n * 4 + hA + 2] = plb;
        d_er[n * 4 + hA]     = pra;
        d_er[n * 4 + hA + 2] = prb;
    }
}

// ---------------- Aggregation: edge softmax + weighted sum (warp per dst node) ----------------
__global__ void k_agg(const float* __restrict__ gat_bias) {
    int gw = (blockIdx.x * blockDim.x + threadIdx.x) >> 5;
    int lane = threadIdx.x & 31;
    if (gw >= Nn) return;
    int n = gw;
    int hA = lane >> 4;

    float4 er4 = ((const float4*)d_er)[n];
    int beg = d_off[n], end = d_off[n + 1];

    // pass 1: per-head max of leaky_relu(el[src]+er[n])
    float m0 = -1e30f, m1 = -1e30f, m2 = -1e30f, m3 = -1e30f;
    for (int i = beg; i < end; i++) {
        int sn = d_esrc[i];
        float4 e4 = ((const float4*)d_el)[sn];
        float e0 = e4.x + er4.x; e0 = e0 > 0.f ? e0 : NEG * e0; m0 = fmaxf(m0, e0);
        float e1 = e4.y + er4.y; e1 = e1 > 0.f ? e1 : NEG * e1; m1 = fmaxf(m1, e1);
        float e2 = e4.z + er4.z; e2 = e2 > 0.f ? e2 : NEG * e2; m2 = fmaxf(m2, e2);
        float e3 = e4.w + er4.w; e3 = e3 > 0.f ? e3 : NEG * e3; m3 = fmaxf(m3, e3);
    }

    // pass 2: exp, sum, weighted feature accumulation
    float s0 = 0.f, s1 = 0.f, s2 = 0.f, s3 = 0.f;
    float4 aA = make_float4(0.f, 0.f, 0.f, 0.f);
    float4 aB = make_float4(0.f, 0.f, 0.f, 0.f);
    for (int i = beg; i < end; i++) {
        int sn = d_esrc[i];
        float4 e4 = ((const float4*)d_el)[sn];
        float e0 = e4.x + er4.x; e0 = e0 > 0.f ? e0 : NEG * e0;
        float e1 = e4.y + er4.y; e1 = e1 > 0.f ? e1 : NEG * e1;
        float e2 = e4.z + er4.z; e2 = e2 > 0.f ? e2 : NEG * e2;
        float e3 = e4.w + er4.w; e3 = e3 > 0.f ? e3 : NEG * e3;
        float w0 = __expf(e0 - m0);
        float w1 = __expf(e1 - m1);
        float w2 = __expf(e2 - m2);
        float w3 = __expf(e3 - m3);
        s0 += w0; s1 += w1; s2 += w2; s3 += w3;
        float wA = hA ? w1 : w0;
        float wB = hA ? w3 : w2;
        float4 fA = ((const float4*)d_feat)[sn * 64 + lane];
        float4 fB = ((const float4*)d_feat)[sn * 64 + 32 + lane];
        aA.x += wA * fA.x; aA.y += wA * fA.y; aA.z += wA * fA.z; aA.w += wA * fA.w;
        aB.x += wB * fB.x; aB.y += wB * fB.y; aB.z += wB * fB.z; aB.w += wB * fB.w;
    }

    float sA = hA ? s1 : s0;
    float sB = hA ? s3 : s2;
    float iA = sA > 0.f ? 1.f / sA : 0.f;
    float iB = sB > 0.f ? 1.f / sB : 0.f;
    float4 bA = ((const float4*)gat_bias)[lane];
    float4 bB = ((const float4*)gat_bias)[32 + lane];
    float4 oA, oB;
    oA.x = aA.x * iA + bA.x; oA.y = aA.y * iA + bA.y;
    oA.z = aA.z * iA + bA.z; oA.w = aA.w * iA + bA.w;
    oB.x = aB.x * iB + bB.x; oB.y = aB.y * iB + bB.y;
    oB.z = aB.z * iB + bB.z; oB.w = aB.w * iB + bB.w;
    ((float4*)d_rst)[n * 64 + lane]      = oA;
    ((float4*)d_rst)[n * 64 + 32 + lane] = oB;
}

// ---------------- GEMM2 + LayerNorm: out = LN(rst @ out_w + out_b) ----------------
// Block = 128 threads (4 warps), 32 nodes/block; warp handles 8 nodes, lane owns cols {2l,2l+1}.
__global__ void k_gemm2(const float* __restrict__ out_w, const float* __restrict__ out_b,
                        const float* __restrict__ ln_g, const float* __restrict__ ln_b,
                        float* __restrict__ out) {
    __shared__ float rs[32 * 256];   // 32 KB
    __shared__ float ws[64 * 64];    // 16 KB (one K-chunk of out_w)
    int t = threadIdx.x;
    int lane = t & 31, warp = t >> 5;
    int node0 = blockIdx.x * 32;

    // load rst tile (32 nodes x 256) coalesced
    #pragma unroll
    for (int i = 0; i < 16; i++) {
        int idx = t + i * 128;               // float4 idx; 64 float4 per node
        int node = node0 + (idx >> 6);
        float4 v = make_float4(0.f, 0.f, 0.f, 0.f);
        if (node < Nn) v = ((const float4*)d_rst)[node * 64 + (idx & 63)];
        ((float4*)rs)[idx] = v;
    }

    float2 acc[8];
    #pragma unroll
    for (int nd = 0; nd < 8; nd++) acc[nd] = make_float2(0.f, 0.f);

    for (int kc = 0; kc < 4; kc++) {
        __syncthreads();
        #pragma unroll
        for (int i = 0; i < 8; i++) {
            int idx = t + i * 128;           // float4 in ws: row=idx>>4, c4=idx&15
            ((float4*)ws)[idx] =
                ((const float4*)out_w)[(kc * 64 + (idx >> 4)) * 16 + (idx & 15)];
        }
        __syncthreads();
        for (int k = 0; k < 64; k++) {
            float2 w2 = ((float2*)ws)[k * 32 + lane];
            #pragma unroll
            for (int nd = 0; nd < 8; nd++) {
                float rv = rs[(warp * 8 + nd) * 256 + kc * 64 + k];
                acc[nd].x += rv * w2.x;
                acc[nd].y += rv * w2.y;
            }
        }
    }

    float2 ob = ((const float2*)out_b)[lane];
    float2 g2 = ((const float2*)ln_g)[lane];
    float2 b2 = ((const float2*)ln_b)[lane];
    #pragma unroll
    for (int nd = 0; nd < 8; nd++) {
        float x0 = acc[nd].x + ob.x;
        float x1 = acc[nd].y + ob.y;
        float p = x0 + x1;
        float q = x0 * x0 + x1 * x1;
        #pragma unroll
        for (int o = 16; o > 0; o >>= 1) {
            p += __shfl_xor_sync(0xffffffffu, p, o);
            q += __shfl_xor_sync(0xffffffffu, q, o);
        }
        float mean = p * (1.f / 64.f);
        float var = q * (1.f / 64.f) - mean * mean;
        float rstd = rsqrtf(var + LNEPS);
        int node = node0 + warp * 8 + nd;
        if (node < Nn) {
            float2 y;
            y.x = (x0 - mean) * rstd * g2.x + b2.x;
            y.y = (x1 - mean) * rstd * g2.y + b2.y;
            ((float2*)out)[node * 32 + lane] = y;
        }
    }
}

// ---------------- launch ----------------
extern "C" void kernel_launch(void* const* d_in, const int* in_sizes, int n_in,
                              void* d_out, int out_size) {
    const float* h        = (const float*)d_in[0];
    const int*   src      = (const int*)d_in[1];
    const int*   dst      = (const int*)d_in[2];
    const float* fc_w     = (const float*)d_in[3];
    const float* attn_l   = (const float*)d_in[4];
    const float* attn_r   = (const float*)d_in[5];
    const float* gat_bias = (const float*)d_in[6];
    const float* out_w    = (const float*)d_in[7];
    const float* out_b    = (const float*)d_in[8];
    const float* ln_g     = (const float*)d_in[9];
    const float* ln_b     = (const float*)d_in[10];
    float* out = (float*)d_out;

    // CSR build
    k_zero<<<(Nn + 255) / 256, 256>>>();
    k_hist<<<(Ee + 255) / 256, 256>>>(dst);
    k_scan<<<1, 1024>>>();
    k_scatter<<<(Ee + 255) / 256, 256>>>(src, dst);

    // GAT pipeline
    k_gemm1<<<(Nn + 63) / 64, 256>>>(h, fc_w);
    k_elr<<<(Nn + 7) / 8, 256>>>(attn_l, attn_r);
    k_agg<<<(Nn + 7) / 8, 256>>>(gat_bias);
    k_gemm2<<<(Nn + 31) / 32, 128>>>(out_w, out_b, ln_g, ln_b, out);
}

// round 2
// speedup vs baseline: 1.0334x; 1.0334x over previous
#include <cuda_runtime.h>
#include <cuda_fp16.h>
#include <mma.h>
#include <math.h>

using namespace nvcuda;

#define Nn 50000
#define Ee 800000
#define NEG 0.2f
#define LNEPS 1e-5f

// ---- scratch (static __device__ arrays: allocation is banned) ----
__device__ __half d_feat_h[Nn * 256];  // GEMM1 output as fp16 [N, H*F]
__device__ float d_el[Nn * 4];         // left attention logits [N, H]
__device__ float d_er[Nn * 4];         // right attention logits [N, H]
__device__ float d_rst[Nn * 256];      // aggregated features [N, H*F]
__device__ int   d_cnt[Nn];
__device__ int   d_off[Nn + 1];
__device__ int   d_cur[Nn];
__device__ int   d_esrc[Ee];           // src ids sorted by dst (CSR payload)

// ---------------- CSR build ----------------
__global__ void k_zero() {
    int i = blockIdx.x * blockDim.x + threadIdx.x;
    if (i < Nn) d_cnt[i] = 0;
}

__global__ void k_hist(const int* __restrict__ dst) {
    int i = blockIdx.x * blockDim.x + threadIdx.x;
    if (i < Ee) atomicAdd(&d_cnt[dst[i]], 1);
}

__global__ void k_scan() {  // single block, 1024 threads
    __shared__ int ps[1024];
    int t = threadIdx.x;
    const int CH = (Nn + 1023) / 1024;  // 49
    int b = t * CH;
    int e = b + CH; if (e > Nn) e = Nn;
    int s = 0;
    for (int i = b; i < e; i++) s += d_cnt[i];
    ps[t] = s;
    __syncthreads();
    for (int o = 1; o < 1024; o <<= 1) {
        int v = (t >= o) ? ps[t - o] : 0;
        __syncthreads();
        ps[t] += v;
        __syncthreads();
    }
    int run = (t == 0) ? 0 : ps[t - 1];
    for (int i = b; i < e; i++) {
        d_off[i] = run;
        d_cur[i] = run;
        run += d_cnt[i];
    }
    if (t == 1023) d_off[Nn] = ps[1023];
}

__global__ void k_scatter(const int* __restrict__ src, const int* __restrict__ dst) {
    int i = blockIdx.x * blockDim.x + threadIdx.x;
    if (i < Ee) {
        int p = atomicAdd(&d_cur[dst[i]], 1);
        d_esrc[p] = src[i];
    }
}

// split a float fragment into tf32 hi/lo parts (error ~2^-24 after 3 MMAs)
template <typename Frag>
__device__ __forceinline__ void split_tf32(Frag& hi, Frag& lo) {
    #pragma unroll
    for (int i = 0; i < hi.num_elements; i++) {
        float f = hi.x[i];
        float fh = wmma::__float_to_tf32(f);
        hi.x[i] = fh;
        lo.x[i] = wmma::__float_to_tf32(f - fh);
    }
}

// ---------------- GEMM1: feat = h @ fc_w ([N,64]@[64,256]), TF32 tensor cores.
// Fused epilogue: fp16 feat store + el/er attention logits.
// Block 256 thr (8 warps), tile 32 nodes x 256 cols; warp = 16x64 (2m x 4n warps).
__global__ void k_gemm1(const float* __restrict__ h, const float* __restrict__ fc_w,
                        const float* __restrict__ attn_l, const float* __restrict__ attn_r) {
    __shared__ __align__(128) float hs[32 * 72];    // h tile, ld=72
    __shared__ __align__(128) float os[32 * 264];   // fp32 out tile, ld=264
    int t = threadIdx.x;
    int lane = t & 31, warp = t >> 5;
    int node0 = blockIdx.x * 32;

    // load h tile (32 nodes x 64 cols), coalesced float4
    #pragma unroll
    for (int i = 0; i < 2; i++) {
        int idx = t + i * 256;              // float4 idx; 16 per node
        int row = idx >> 4, c4 = idx & 15;
        float4 v = make_float4(0.f, 0.f, 0.f, 0.f);
        int node = node0 + row;
        if (node < Nn) v = ((const float4*)h)[node * 16 + c4];
        *(float4*)&hs[row * 72 + c4 * 4] = v;
    }
    __syncthreads();

    int wm = warp >> 2;           // 0..1 (16-node slab)
    int wn = warp & 3;            // 0..3 (64-col slab)

    wmma::fragment<wmma::matrix_a, 16, 16, 8, wmma::precision::tf32, wmma::row_major> fa, fal;
    wmma::fragment<wmma::matrix_b, 16, 16, 8, wmma::precision::tf32, wmma::row_major> fb, fbl;
    wmma::fragment<wmma::accumulator, 16, 16, 8, float> fc[4];
    #pragma unroll
    for (int j = 0; j < 4; j++) wmma::fill_fragment(fc[j], 0.f);

    #pragma unroll
    for (int k0 = 0; k0 < 8; k0++) {
        wmma::load_matrix_sync(fa, &hs[wm * 16 * 72 + k0 * 8], 72);
        split_tf32(fa, fal);
        #pragma unroll
        for (int j = 0; j < 4; j++) {
            wmma::load_matrix_sync(fb, fc_w + k0 * 8 * 256 + wn * 64 + j * 16, 256);
            split_tf32(fb, fbl);
            wmma::mma_sync(fc[j], fa, fb, fc[j]);
            wmma::mma_sync(fc[j], fa, fbl, fc[j]);
            wmma::mma_sync(fc[j], fal, fb, fc[j]);
        }
    }
    #pragma unroll
    for (int j = 0; j < 4; j++)
        wmma::store_matrix_sync(&os[wm * 16 * 264 + wn * 64 + j * 16], fc[j], 264,
                                wmma::mem_row_major);
    __syncthreads();

    // epilogue: each warp handles 4 nodes; lane owns 8 cols (one head: lane>>3)
    float4 al0 = ((const float4*)attn_l)[lane * 2];
    float4 al1 = ((const float4*)attn_l)[lane * 2 + 1];
    float4 ar0 = ((const float4*)attn_r)[lane * 2];
    float4 ar1 = ((const float4*)attn_r)[lane * 2 + 1];
    #pragma unroll
    for (int q = 0; q < 4; q++) {
        int r = warp * 4 + q;
        int node = node0 + r;
        float4 v0 = *(float4*)&os[r * 264 + lane * 8];
        float4 v1 = *(float4*)&os[r * 264 + lane * 8 + 4];
        float pl = v0.x * al0.x + v0.y * al0.y + v0.z * al0.z + v0.w * al0.w +
                   v1.x * al1.x + v1.y * al1.y + v1.z * al1.z + v1.w * al1.w;
        float pr = v0.x * ar0.x + v0.y * ar0.y + v0.z * ar0.z + v0.w * ar0.w +
                   v1.x * ar1.x + v1.y * ar1.y + v1.z * ar1.z + v1.w * ar1.w;
        #pragma unroll
        for (int o = 4; o > 0; o >>= 1) {  // reduce within 8-lane head groups
            pl += __shfl_xor_sync(0xffffffffu, pl, o);
            pr += __shfl_xor_sync(0xffffffffu, pr, o);
        }
        if (node < Nn) {
            __half2 p[4];
            p[0] = __floats2half2_rn(v0.x, v0.y);
            p[1] = __floats2half2_rn(v0.z, v0.w);
            p[2] = __floats2half2_rn(v1.x, v1.y);
            p[3] = __floats2half2_rn(v1.z, v1.w);
            *(uint4*)&d_feat_h[node * 256 + lane * 8] = *(uint4*)p;
            if ((lane & 7) == 0) {
                int head = lane >> 3;
                d_el[node * 4 + head] = pl;
                d_er[node * 4 + head] = pr;
            }
        }
    }
}

// ---------------- Aggregation: one-pass edge softmax + weighted sum (warp/dst) --------
__global__ void k_agg(const float* __restrict__ gat_bias) {
    int gw = (blockIdx.x * blockDim.x + threadIdx.x) >> 5;
    int lane = threadIdx.x & 31;
    if (gw >= Nn) return;
    int n = gw;
    int hA = lane >> 4;

    float4 er4 = ((const float4*)d_er)[n];
    int beg = d_off[n], end = d_off[n + 1];

    float s0 = 0.f, s1 = 0.f, s2 = 0.f, s3 = 0.f;
    float4 aA = make_float4(0.f, 0.f, 0.f, 0.f);
    float4 aB = make_float4(0.f, 0.f, 0.f, 0.f);
    for (int i = beg; i < end; i++) {
        int sn = d_esrc[i];
        float4 e4 = ((const float4*)d_el)[sn];
        float e0 = e4.x + er4.x; e0 = e0 > 0.f ? e0 : NEG * e0;
        float e1 = e4.y + er4.y; e1 = e1 > 0.f ? e1 : NEG * e1;
        float e2 = e4.z + er4.z; e2 = e2 > 0.f ? e2 : NEG * e2;
        float e3 = e4.w + er4.w; e3 = e3 > 0.f ? e3 : NEG * e3;
        // logits are small (|e| < ~8): exp cannot overflow, skip max-subtraction
        float w0 = __expf(e0);
        float w1 = __expf(e1);
        float w2 = __expf(e2);
        float w3 = __expf(e3);
        s0 += w0; s1 += w1; s2 += w2; s3 += w3;
        float wA = hA ? w1 : w0;
        float wB = hA ? w3 : w2;
        const __half2* fp = (const __half2*)(d_feat_h + (size_t)sn * 256);
        uint2 ua = *(const uint2*)(fp + 2 * lane);
        uint2 ub = *(const uint2*)(fp + 64 + 2 * lane);
        float2 fa0 = __half22float2(*(__half2*)&ua.x);
        float2 fa1 = __half22float2(*(__half2*)&ua.y);
        float2 fb0 = __half22float2(*(__half2*)&ub.x);
        float2 fb1 = __half22float2(*(__half2*)&ub.y);
        aA.x += wA * fa0.x; aA.y += wA * fa0.y; aA.z += wA * fa1.x; aA.w += wA * fa1.y;
        aB.x += wB * fb0.x; aB.y += wB * fb0.y; aB.z += wB * fb1.x; aB.w += wB * fb1.y;
    }

    float sA = hA ? s1 : s0;
    float sB = hA ? s3 : s2;
    float iA = sA > 0.f ? 1.f / sA : 0.f;
    float iB = sB > 0.f ? 1.f / sB : 0.f;
    float4 bA = ((const float4*)gat_bias)[lane];
    float4 bB = ((const float4*)gat_bias)[32 + lane];
    float4 oA, oB;
    oA.x = aA.x * iA + bA.x; oA.y = aA.y * iA + bA.y;
    oA.z = aA.z * iA + bA.z; oA.w = aA.w * iA + bA.w;
    oB.x = aB.x * iB + bB.x; oB.y = aB.y * iB + bB.y;
    oB.z = aB.z * iB + bB.z; oB.w = aB.w * iB + bB.w;
    ((float4*)d_rst)[n * 64 + lane]      = oA;
    ((float4*)d_rst)[n * 64 + 32 + lane] = oB;
}

// ---------------- GEMM2 + LayerNorm: out = LN(rst @ out_w + out_b), TF32 ----------------
// Block 256 thr (8 warps), tile 32 nodes x 64 cols; warp = 16x16 (2m x 4n warps). K=256.
__global__ void k_gemm2(const float* __restrict__ out_w, const float* __restrict__ out_b,
                        const float* __restrict__ ln_g, const float* __restrict__ ln_b,
                        float* __restrict__ out) {
    __shared__ __align__(128) float rs[32 * 264];   // rst tile, ld=264
    __shared__ __align__(128) float os[32 * 72];    // fp32 out tile, ld=72
    int t = threadIdx.x;
    int lane = t & 31, warp = t >> 5;
    int node0 = blockIdx.x * 32;

    // load rst tile (32 nodes x 256), coalesced float4
    #pragma unroll
    for (int i = 0; i < 8; i++) {
        int idx = t + i * 256;              // float4 idx; 64 per node
        int row = idx >> 6, c4 = idx & 63;
        float4 v = make_float4(0.f, 0.f, 0.f, 0.f);
        int node = node0 + row;
        if (node < Nn) v = ((const float4*)d_rst)[node * 64 + c4];
        *(float4*)&rs[row * 264 + c4 * 4] = v;
    }
    __syncthreads();

    int wm = warp >> 2;           // 0..1
    int wn = warp & 3;            // 0..3

    wmma::fragment<wmma::matrix_a, 16, 16, 8, wmma::precision::tf32, wmma::row_major> fa, fal;
    wmma::fragment<wmma::matrix_b, 16, 16, 8, wmma::precision::tf32, wmma::row_major> fb, fbl;
    wmma::fragment<wmma::accumulator, 16, 16, 8, float> fc;
    wmma::fill_fragment(fc, 0.f);

    #pragma unroll
    for (int k0 = 0; k0 < 32; k0++) {
        wmma::load_matrix_sync(fa, &rs[wm * 16 * 264 + k0 * 8], 264);
        split_tf32(fa, fal);
        wmma::load_matrix_sync(fb, out_w + k0 * 8 * 64 + wn * 16, 64);
        split_tf32(fb, fbl);
        wmma::mma_sync(fc, fa, fb, fc);
        wmma::mma_sync(fc, fa, fbl, fc);
        wmma::mma_sync(fc, fal, fb, fc);
    }
    wmma::store_matrix_sync(&os[wm * 16 * 72 + wn * 16], fc, 72, wmma::mem_row_major);
    __syncthreads();

    // LayerNorm epilogue: warp handles 4 nodes; lane owns cols {2l, 2l+1}
    float2 ob = ((const float2*)out_b)[lane];
    float2 g2 = ((const float2*)ln_g)[lane];
    float2 b2 = ((const float2*)ln_b)[lane];
    #pragma unroll
    for (int q = 0; q < 4; q++) {
        int r = warp * 4 + q;
        int node = node0 + r;
        float2 v = *(float2*)&os[r * 72 + lane * 2];
        float x0 = v.x + ob.x;
        float x1 = v.y + ob.y;
        float p = x0 + x1;
        float s = x0 * x0 + x1 * x1;
        #pragma unroll
        for (int o = 16; o > 0; o >>= 1) {
            p += __shfl_xor_sync(0xffffffffu, p, o);
            s += __shfl_xor_sync(0xffffffffu, s, o);
        }
        float mean = p * (1.f / 64.f);
        float var = s * (1.f / 64.f) - mean * mean;
        float rstd = rsqrtf(var + LNEPS);
        if (node < Nn) {
            float2 y;
            y.x = (x0 - mean) * rstd * g2.x + b2.x;
            y.y = (x1 - mean) * rstd * g2.y + b2.y;
            ((float2*)out)[node * 32 + lane] = y;
        }
    }
}

// ---------------- launch ----------------
extern "C" void kernel_launch(void* const* d_in, const int* in_sizes, int n_in,
                              void* d_out, int out_size) {
    const float* h        = (const float*)d_in[0];
    const int*   src      = (const int*)d_in[1];
    const int*   dst      = (const int*)d_in[2];
    const float* fc_w     = (const float*)d_in[3];
    const float* attn_l   = (const float*)d_in[4];
    const float* attn_r   = (const float*)d_in[5];
    const float* gat_bias = (const float*)d_in[6];
    const float* out_w    = (const float*)d_in[7];
    const float* out_b    = (const float*)d_in[8];
    const float* ln_g     = (const float*)d_in[9];
    const float* ln_b     = (const float*)d_in[10];
    float* out = (float*)d_out;

    // CSR build
    k_zero<<<(Nn + 255) / 256, 256>>>();
    k_hist<<<(Ee + 255) / 256, 256>>>(dst);
    k_scan<<<1, 1024>>>();
    k_scatter<<<(Ee + 255) / 256, 256>>>(src, dst);

    // GAT pipeline
    k_gemm1<<<(Nn + 31) / 32, 256>>>(h, fc_w, attn_l, attn_r);
    k_agg<<<(Nn + 7) / 8, 256>>>(gat_bias);
    k_gemm2<<<(Nn + 31) / 32, 256>>>(out_w, out_b, ln_g, ln_b, out);
}

// round 3
// speedup vs baseline: 1.3799x; 1.3353x over previous
#include <cuda_runtime.h>
#include <cuda_fp16.h>
#include <mma.h>
#include <math.h>

using namespace nvcuda;

#define Nn 50000
#define Ee 800000
#define NEG 0.2f
#define LNEPS 1e-5f
#define SCAN_BLOCKS ((Nn + 1023) / 1024)   // 49

// ---- scratch (static __device__ arrays: allocation is banned) ----
__device__ __half d_feat_h[Nn * 256];  // GEMM1 output as fp16 [N, H*F]
__device__ float d_el[Nn * 4];         // left attention logits [N, H]
__device__ float d_er[Nn * 4];         // right attention logits [N, H]
__device__ float d_rst[Nn * 256];      // aggregated features [N, H*F]
__device__ float4 d_w[Ee];             // per-edge unnormalized softmax weights
__device__ int   d_cnt[Nn];            // zero-init at load; re-zeroed each call
__device__ int   d_off[Nn + 1];
__device__ int   d_cur[Nn];
__device__ int   d_bsum[SCAN_BLOCKS];
__device__ int   d_bbase[SCAN_BLOCKS];
__device__ int   d_esrc[Ee];           // src ids sorted by dst (CSR payload)

// ---------------- CSR build ----------------
__global__ void k_hist(const int* __restrict__ dst) {
    int i = blockIdx.x * blockDim.x + threadIdx.x;
    if (i < Ee) atomicAdd(&d_cnt[dst[i]], 1);
}

// phase 1: coalesced block-local exclusive scan + block sums (49 blocks x 1024)
__global__ void k_scan_part() {
    __shared__ int wsum[32];
    int t = threadIdx.x, b = blockIdx.x;
    int lane = t & 31, wid = t >> 5;
    int i = b * 1024 + t;
    int v = (i < Nn) ? d_cnt[i] : 0;
    int x = v;
    #pragma unroll
    for (int o = 1; o < 32; o <<= 1) {
        int y = __shfl_up_sync(0xffffffffu, x, o);
        if (lane >= o) x += y;
    }
    if (lane == 31) wsum[wid] = x;
    __syncthreads();
    if (wid == 0) {
        int s = wsum[lane];
        #pragma unroll
        for (int o = 1; o < 32; o <<= 1) {
            int y = __shfl_up_sync(0xffffffffu, s, o);
            if (lane >= o) s += y;
        }
        wsum[lane] = s;
    }
    __syncthreads();
    int base = wid ? wsum[wid - 1] : 0;
    if (i < Nn) d_off[i] = base + x - v;   // block-local exclusive scan (temp)
    if (t == 0) d_bsum[b] = wsum[31];
}

// phase 2: scan the 49 block sums (1 tiny block)
__global__ void k_scan_top() {
    int t = threadIdx.x;   // 64 threads
    int v = (t < SCAN_BLOCKS) ? d_bsum[t] : 0;
    int x = v;
    #pragma unroll
    for (int o = 1; o < 64; o <<= 1) {
        int y = __shfl_up_sync(0xffffffffu, x, o);   // 64 > 32: do in two warps
        if ((t & 31) >= o && o < 32) x += y;
    }
    // cross-warp fixup via shared
    __shared__ int w0tot;
    if (t == 31) w0tot = x;
    __syncthreads();
    if (t >= 32) x += w0tot;
    if (t < SCAN_BLOCKS) d_bbase[t] = x - v;         // exclusive
    if (t == SCAN_BLOCKS - 1) d_off[Nn] = x;         // total
}

// phase 3: add block bases, init cursors, re-zero d_cnt for next call
__global__ void k_scan_final() {
    int t = threadIdx.x, b = blockIdx.x;
    int i = b * 1024 + t;
    if (i < Nn) {
        int off = d_off[i] + d_bbase[b];
        d_off[i] = off;
        d_cur[i] = off;
        d_cnt[i] = 0;
    }
}

// scatter + per-edge softmax weight (needs el/er from gemm1)
__global__ void k_scatterw(const int* __restrict__ src, const int* __restrict__ dst) {
    int i = blockIdx.x * blockDim.x + threadIdx.x;
    if (i >= Ee) return;
    int s = src[i], d = dst[i];
    float4 el4 = ((const float4*)d_el)[s];
    float4 er4 = ((const float4*)d_er)[d];
    float e0 = el4.x + er4.x; e0 = e0 > 0.f ? e0 : NEG * e0;
    float e1 = el4.y + er4.y; e1 = e1 > 0.f ? e1 : NEG * e1;
    float e2 = el4.z + er4.z; e2 = e2 > 0.f ? e2 : NEG * e2;
    float e3 = el4.w + er4.w; e3 = e3 > 0.f ? e3 : NEG * e3;
    // logits small (|e| < ~8): exp cannot overflow; skip max-subtraction
    int p = atomicAdd(&d_cur[d], 1);
    d_esrc[p] = s;
    d_w[p] = make_float4(__expf(e0), __expf(e1), __expf(e2), __expf(e3));
}

// split a float fragment into tf32 hi/lo parts
template <typename Frag>
__device__ __forceinline__ void split_tf32(Frag& hi, Frag& lo) {
    #pragma unroll
    for (int i = 0; i < hi.num_elements; i++) {
        float f = hi.x[i];
        float fh = wmma::__float_to_tf32(f);
        hi.x[i] = fh;
        lo.x[i] = wmma::__float_to_tf32(f - fh);
    }
}

// ---------------- GEMM1: feat = h @ fc_w ([N,64]@[64,256]), TF32 tensor cores.
// Fused epilogue: fp16 feat store + el/er attention logits.
__global__ void k_gemm1(const float* __restrict__ h, const float* __restrict__ fc_w,
                        const float* __restrict__ attn_l, const float* __restrict__ attn_r) {
    __shared__ __align__(128) float hs[32 * 72];    // h tile, ld=72
    __shared__ __align__(128) float os[32 * 264];   // fp32 out tile, ld=264
    int t = threadIdx.x;
    int lane = t & 31, warp = t >> 5;
    int node0 = blockIdx.x * 32;

    #pragma unroll
    for (int i = 0; i < 2; i++) {
        int idx = t + i * 256;              // float4 idx; 16 per node
        int row = idx >> 4, c4 = idx & 15;
        float4 v = make_float4(0.f, 0.f, 0.f, 0.f);
        int node = node0 + row;
        if (node < Nn) v = ((const float4*)h)[node * 16 + c4];
        *(float4*)&hs[row * 72 + c4 * 4] = v;
    }
    __syncthreads();

    int wm = warp >> 2, wn = warp & 3;

    wmma::fragment<wmma::matrix_a, 16, 16, 8, wmma::precision::tf32, wmma::row_major> fa, fal;
    wmma::fragment<wmma::matrix_b, 16, 16, 8, wmma::precision::tf32, wmma::row_major> fb, fbl;
    wmma::fragment<wmma::accumulator, 16, 16, 8, float> fc[4];
    #pragma unroll
    for (int j = 0; j < 4; j++) wmma::fill_fragment(fc[j], 0.f);

    #pragma unroll
    for (int k0 = 0; k0 < 8; k0++) {
        wmma::load_matrix_sync(fa, &hs[wm * 16 * 72 + k0 * 8], 72);
        split_tf32(fa, fal);
        #pragma unroll
        for (int j = 0; j < 4; j++) {
            wmma::load_matrix_sync(fb, fc_w + k0 * 8 * 256 + wn * 64 + j * 16, 256);
            split_tf32(fb, fbl);
            wmma::mma_sync(fc[j], fa, fb, fc[j]);
            wmma::mma_sync(fc[j], fa, fbl, fc[j]);
            wmma::mma_sync(fc[j], fal, fb, fc[j]);
        }
    }
    #pragma unroll
    for (int j = 0; j < 4; j++)
        wmma::store_matrix_sync(&os[wm * 16 * 264 + wn * 64 + j * 16], fc[j], 264,
                                wmma::mem_row_major);
    __syncthreads();

    float4 al0 = ((const float4*)attn_l)[lane * 2];
    float4 al1 = ((const float4*)attn_l)[lane * 2 + 1];
    float4 ar0 = ((const float4*)attn_r)[lane * 2];
    float4 ar1 = ((const float4*)attn_r)[lane * 2 + 1];
    #pragma unroll
    for (int q = 0; q < 4; q++) {
        int r = warp * 4 + q;
        int node = node0 + r;
        float4 v0 = *(float4*)&os[r * 264 + lane * 8];
        float4 v1 = *(float4*)&os[r * 264 + lane * 8 + 4];
        float pl = v0.x * al0.x + v0.y * al0.y + v0.z * al0.z + v0.w * al0.w +
                   v1.x * al1.x + v1.y * al1.y + v1.z * al1.z + v1.w * al1.w;
        float pr = v0.x * ar0.x + v0.y * ar0.y + v0.z * ar0.z + v0.w * ar0.w +
                   v1.x * ar1.x + v1.y * ar1.y + v1.z * ar1.z + v1.w * ar1.w;
        #pragma unroll
        for (int o = 4; o > 0; o >>= 1) {
            pl += __shfl_xor_sync(0xffffffffu, pl, o);
            pr += __shfl_xor_sync(0xffffffffu, pr, o);
        }
        if (node < Nn) {
            __half2 p[4];
            p[0] = __floats2half2_rn(v0.x, v0.y);
            p[1] = __floats2half2_rn(v0.z, v0.w);
            p[2] = __floats2half2_rn(v1.x, v1.y);
            p[3] = __floats2half2_rn(v1.z, v1.w);
            *(uint4*)&d_feat_h[node * 256 + lane * 8] = *(uint4*)p;
            if ((lane & 7) == 0) {
                int head = lane >> 3;
                d_el[node * 4 + head] = pl;
                d_er[node * 4 + head] = pr;
            }
        }
    }
}

// ---------------- Gather: acc += w*feat, s += w; scale by 1/s at end (warp/dst) ----
__global__ void k_gather(const float* __restrict__ gat_bias) {
    int gw = (blockIdx.x * blockDim.x + threadIdx.x) >> 5;
    int lane = threadIdx.x & 31;
    if (gw >= Nn) return;
    int n = gw;
    int hA = lane >> 4;

    int beg = d_off[n], end = d_off[n + 1];
    float sA = 0.f, sB = 0.f;
    float4 aA = make_float4(0.f, 0.f, 0.f, 0.f);
    float4 aB = make_float4(0.f, 0.f, 0.f, 0.f);
    for (int i = beg; i < end; i++) {
        int sn = d_esrc[i];
        float4 w4 = d_w[i];
        float wA = hA ? w4.y : w4.x;
        float wB = hA ? w4.w : w4.z;
        sA += wA; sB += wB;
        const __half2* fp = (const __half2*)(d_feat_h + (size_t)sn * 256);
        uint2 ua = *(const uint2*)(fp + 2 * lane);
        uint2 ub = *(const uint2*)(fp + 64 + 2 * lane);
        float2 fa0 = __half22float2(*(__half2*)&ua.x);
        float2 fa1 = __half22float2(*(__half2*)&ua.y);
        float2 fb0 = __half22float2(*(__half2*)&ub.x);
        float2 fb1 = __half22float2(*(__half2*)&ub.y);
        aA.x += wA * fa0.x; aA.y += wA * fa0.y; aA.z += wA * fa1.x; aA.w += wA * fa1.y;
        aB.x += wB * fb0.x; aB.y += wB * fb0.y; aB.z += wB * fb1.x; aB.w += wB * fb1.y;
    }

    float iA = sA > 0.f ? 1.f / sA : 0.f;
    float iB = sB > 0.f ? 1.f / sB : 0.f;
    float4 bA = ((const float4*)gat_bias)[lane];
    float4 bB = ((const float4*)gat_bias)[32 + lane];
    float4 oA, oB;
    oA.x = aA.x * iA + bA.x; oA.y = aA.y * iA + bA.y;
    oA.z = aA.z * iA + bA.z; oA.w = aA.w * iA + bA.w;
    oB.x = aB.x * iB + bB.x; oB.y = aB.y * iB + bB.y;
    oB.z = aB.z * iB + bB.z; oB.w = aB.w * iB + bB.w;
    ((float4*)d_rst)[n * 64 + lane]      = oA;
    ((float4*)d_rst)[n * 64 + 32 + lane] = oB;
}

// ---------------- GEMM2 + LayerNorm: out = LN(rst @ out_w + out_b), TF32 ----------------
__global__ void k_gemm2(const float* __restrict__ out_w, const float* __restrict__ out_b,
                        const float* __restrict__ ln_g, const float* __restrict__ ln_b,
                        float* __restrict__ out) {
    __shared__ __align__(128) float rs[32 * 264];
    __shared__ __align__(128) float os[32 * 72];
    int t = threadIdx.x;
    int lane = t & 31, warp = t >> 5;
    int node0 = blockIdx.x * 32;

    #pragma unroll
    for (int i = 0; i < 8; i++) {
        int idx = t + i * 256;
        int row = idx >> 6, c4 = idx & 63;
        float4 v = make_float4(0.f, 0.f, 0.f, 0.f);
        int node = node0 + row;
        if (node < Nn) v = ((const float4*)d_rst)[node * 64 + c4];
        *(float4*)&rs[row * 264 + c4 * 4] = v;
    }
    __syncthreads();

    int wm = warp >> 2, wn = warp & 3;

    wmma::fragment<wmma::matrix_a, 16, 16, 8, wmma::precision::tf32, wmma::row_major> fa, fal;
    wmma::fragment<wmma::matrix_b, 16, 16, 8, wmma::precision::tf32, wmma::row_major> fb, fbl;
    wmma::fragment<wmma::accumulator, 16, 16, 8, float> fc;
    wmma::fill_fragment(fc, 0.f);

    #pragma unroll
    for (int k0 = 0; k0 < 32; k0++) {
        wmma::load_matrix_sync(fa, &rs[wm * 16 * 264 + k0 * 8], 264);
        split_tf32(fa, fal);
        wmma::load_matrix_sync(fb, out_w + k0 * 8 * 64 + wn * 16, 64);
        split_tf32(fb, fbl);
        wmma::mma_sync(fc, fa, fb, fc);
        wmma::mma_sync(fc, fa, fbl, fc);
        wmma::mma_sync(fc, fal, fb, fc);
    }
    wmma::store_matrix_sync(&os[wm * 16 * 72 + wn * 16], fc, 72, wmma::mem_row_major);
    __syncthreads();

    float2 ob = ((const float2*)out_b)[lane];
    float2 g2 = ((const float2*)ln_g)[lane];
    float2 b2 = ((const float2*)ln_b)[lane];
    #pragma unroll
    for (int q = 0; q < 4; q++) {
        int r = warp * 4 + q;
        int node = node0 + r;
        float2 v = *(float2*)&os[r * 72 + lane * 2];
        float x0 = v.x + ob.x;
        float x1 = v.y + ob.y;
        float p = x0 + x1;
        float s = x0 * x0 + x1 * x1;
        #pragma unroll
        for (int o = 16; o > 0; o >>= 1) {
            p += __shfl_xor_sync(0xffffffffu, p, o);
            s += __shfl_xor_sync(0xffffffffu, s, o);
        }
        float mean = p * (1.f / 64.f);
        float var = s * (1.f / 64.f) - mean * mean;
        float rstd = rsqrtf(var + LNEPS);
        if (node < Nn) {
            float2 y;
            y.x = (x0 - mean) * rstd * g2.x + b2.x;
            y.y = (x1 - mean) * rstd * g2.y + b2.y;
            ((float2*)out)[node * 32 + lane] = y;
        }
    }
}

// ---------------- launch ----------------
extern "C" void kernel_launch(void* const* d_in, const int* in_sizes, int n_in,
                              void* d_out, int out_size) {
    const float* h        = (const float*)d_in[0];
    const int*   src      = (const int*)d_in[1];
    const int*   dst      = (const int*)d_in[2];
    const float* fc_w     = (const float*)d_in[3];
    const float* attn_l   = (const float*)d_in[4];
    const float* attn_r   = (const float*)d_in[5];
    const float* gat_bias = (const float*)d_in[6];
    const float* out_w    = (const float*)d_in[7];
    const float* out_b    = (const float*)d_in[8];
    const float* ln_g     = (const float*)d_in[9];
    const float* ln_b     = (const float*)d_in[10];
    float* out = (float*)d_out;

    // d_cnt is zero on entry: zero-initialized at module load, re-zeroed by
    // k_scan_final at the end of every call (deterministic, rebuilt each call).
    k_hist<<<(Ee + 255) / 256, 256>>>(dst);
    k_scan_part<<<SCAN_BLOCKS, 1024>>>();
    k_scan_top<<<1, 64>>>();
    k_gemm1<<<(Nn + 31) / 32, 256>>>(h, fc_w, attn_l, attn_r);   // at capture slot
    k_scan_final<<<SCAN_BLOCKS, 1024>>>();
    k_scatterw<<<(Ee + 255) / 256, 256>>>(src, dst);
    k_gather<<<(Nn + 7) / 8, 256>>>(gat_bias);
    k_gemm2<<<(Nn + 31) / 32, 256>>>(out_w, out_b, ln_g, ln_b, out);
}

// round 4
// speedup vs baseline: 1.3801x; 1.0001x over previous
#include <cuda_runtime.h>
#include <cuda_fp16.h>
#include <mma.h>
#include <math.h>

using namespace nvcuda;

#define Nn 50000
#define Ee 800000
#define NEG 0.2f
#define LNEPS 1e-5f
#define SCAN_BLOCKS ((Nn + 1023) / 1024)   // 49

// ---- scratch (static __device__ arrays: allocation is banned) ----
__device__ __half d_feat_h[Nn * 256];   // GEMM1 output as fp16 [N, H*F]
__device__ float d_el[Nn * 4];
__device__ float d_er[Nn * 4];
__device__ __half d_rst_hi[Nn * 256];   // aggregated features, fp16 hi part
__device__ __half d_rst_lo[Nn * 256];   // fp16 lo (residual) part
__device__ __half d_w1hi[64 * 256];     // fc_w split
__device__ __half d_w1lo[64 * 256];
__device__ __half d_w2hi[256 * 64];     // out_w split
__device__ __half d_w2lo[256 * 64];
__device__ float4 d_w[Ee];              // per-edge unnormalized softmax weights
__device__ int   d_cnt[Nn];             // zero-init at load; re-zeroed each call
__device__ int   d_off[Nn + 1];
__device__ int   d_cur[Nn];
__device__ int   d_bsum[SCAN_BLOCKS];
__device__ int   d_bbase[SCAN_BLOCKS];
__device__ int   d_esrc[Ee];

// ---------------- weight pre-split (both are 16384 elements) ----------------
__global__ void k_splitw(const float* __restrict__ fc_w, const float* __restrict__ out_w) {
    int i = blockIdx.x * blockDim.x + threadIdx.x;
    if (i < 64 * 256) {
        float f1 = fc_w[i];
        __half h1 = __float2half_rn(f1);
        d_w1hi[i] = h1;
        d_w1lo[i] = __float2half_rn(f1 - __half2float(h1));
        float f2 = out_w[i];
        __half h2 = __float2half_rn(f2);
        d_w2hi[i] = h2;
        d_w2lo[i] = __float2half_rn(f2 - __half2float(h2));
    }
}

// ---------------- CSR build ----------------
__global__ void k_hist(const int* __restrict__ dst) {
    int i = blockIdx.x * blockDim.x + threadIdx.x;
    if (i < Ee) atomicAdd(&d_cnt[dst[i]], 1);
}

__global__ void k_scan_part() {
    __shared__ int wsum[32];
    int t = threadIdx.x, b = blockIdx.x;
    int lane = t & 31, wid = t >> 5;
    int i = b * 1024 + t;
    int v = (i < Nn) ? d_cnt[i] : 0;
    int x = v;
    #pragma unroll
    for (int o = 1; o < 32; o <<= 1) {
        int y = __shfl_up_sync(0xffffffffu, x, o);
        if (lane >= o) x += y;
    }
    if (lane == 31) wsum[wid] = x;
    __syncthreads();
    if (wid == 0) {
        int s = wsum[lane];
        #pragma unroll
        for (int o = 1; o < 32; o <<= 1) {
            int y = __shfl_up_sync(0xffffffffu, s, o);
            if (lane >= o) s += y;
        }
        wsum[lane] = s;
    }
    __syncthreads();
    int base = wid ? wsum[wid - 1] : 0;
    if (i < Nn) d_off[i] = base + x - v;
    if (t == 0) d_bsum[b] = wsum[31];
}

__global__ void k_scan_top() {
    int t = threadIdx.x;   // 64 threads
    int v = (t < SCAN_BLOCKS) ? d_bsum[t] : 0;
    int x = v;
    #pragma unroll
    for (int o = 1; o < 64; o <<= 1) {
        int y = __shfl_up_sync(0xffffffffu, x, o);
        if ((t & 31) >= o && o < 32) x += y;
    }
    __shared__ int w0tot;
    if (t == 31) w0tot = x;
    __syncthreads();
    if (t >= 32) x += w0tot;
    if (t < SCAN_BLOCKS) d_bbase[t] = x - v;
    if (t == SCAN_BLOCKS - 1) d_off[Nn] = x;
}

__global__ void k_scan_final() {
    int t = threadIdx.x, b = blockIdx.x;
    int i = b * 1024 + t;
    if (i < Nn) {
        int off = d_off[i] + d_bbase[b];
        d_off[i] = off;
        d_cur[i] = off;
        d_cnt[i] = 0;
    }
}

__global__ void k_scatterw(const int* __restrict__ src, const int* __restrict__ dst) {
    int i = blockIdx.x * blockDim.x + threadIdx.x;
    if (i >= Ee) return;
    int s = src[i], d = dst[i];
    float4 el4 = ((const float4*)d_el)[s];
    float4 er4 = ((const float4*)d_er)[d];
    float e0 = el4.x + er4.x; e0 = e0 > 0.f ? e0 : NEG * e0;
    float e1 = el4.y + er4.y; e1 = e1 > 0.f ? e1 : NEG * e1;
    float e2 = el4.z + er4.z; e2 = e2 > 0.f ? e2 : NEG * e2;
    float e3 = el4.w + er4.w; e3 = e3 > 0.f ? e3 : NEG * e3;
    int p = atomicAdd(&d_cur[d], 1);
    d_esrc[p] = s;
    d_w[p] = make_float4(__expf(e0), __expf(e1), __expf(e2), __expf(e3));
}

// ---------------- GEMM1: feat = h @ fc_w, fp16 split MMA (3 products) ----------------
// Block 256 thr (8 warps), 32 nodes x 256 cols; wm=warp>>2, warp covers 64 cols.
__global__ void k_gemm1(const float* __restrict__ h,
                        const float* __restrict__ attn_l, const float* __restrict__ attn_r) {
    __shared__ __align__(128) float sm[32 * 264];          // 33.8 KB, aliased
    __half* hs_hi = (__half*)sm;                            // 32 x 72 halves
    __half* hs_lo = hs_hi + 32 * 72;
    float* os = sm;                                         // 32 x 264 fp32 (after k-loop)
    int t = threadIdx.x;
    int lane = t & 31, warp = t >> 5;
    int node0 = blockIdx.x * 32;

    // load h tile (32 nodes x 64), split fp32 -> fp16 hi/lo
    #pragma unroll
    for (int i = 0; i < 2; i++) {
        int idx = t + i * 256;              // float4 idx; 16 per node
        int row = idx >> 4, c4 = idx & 15;
        float4 v = make_float4(0.f, 0.f, 0.f, 0.f);
        int node = node0 + row;
        if (node < Nn) v = ((const float4*)h)[node * 16 + c4];
        __half h0 = __float2half_rn(v.x), h1 = __float2half_rn(v.y);
        __half h2 = __float2half_rn(v.z), h3 = __float2half_rn(v.w);
        __half2 ph[2] = {__halves2half2(h0, h1), __halves2half2(h2, h3)};
        __half2 pl[2] = {
            __halves2half2(__float2half_rn(v.x - __half2float(h0)),
                           __float2half_rn(v.y - __half2float(h1))),
            __halves2half2(__float2half_rn(v.z - __half2float(h2)),
                           __float2half_rn(v.w - __half2float(h3)))};
        *(uint2*)&hs_hi[row * 72 + c4 * 4] = *(uint2*)ph;
        *(uint2*)&hs_lo[row * 72 + c4 * 4] = *(uint2*)pl;
    }
    __syncthreads();

    int wm = warp >> 2, wc = (warp & 3) * 64;

    wmma::fragment<wmma::matrix_a, 16, 16, 16, __half, wmma::row_major> fah, fal;
    wmma::fragment<wmma::matrix_b, 16, 16, 16, __half, wmma::row_major> fbh, fbl;
    wmma::fragment<wmma::accumulator, 16, 16, 16, float> fc[4];
    #pragma unroll
    for (int j = 0; j < 4; j++) wmma::fill_fragment(fc[j], 0.f);

    #pragma unroll
    for (int k0 = 0; k0 < 4; k0++) {
        wmma::load_matrix_sync(fah, hs_hi + wm * 16 * 72 + k0 * 16, 72);
        wmma::load_matrix_sync(fal, hs_lo + wm * 16 * 72 + k0 * 16, 72);
        #pragma unroll
        for (int j = 0; j < 4; j++) {
            const __half* bp = d_w1hi + k0 * 16 * 256 + wc + j * 16;
            wmma::load_matrix_sync(fbh, bp, 256);
            wmma::load_matrix_sync(fbl, d_w1lo + (bp - d_w1hi), 256);
            wmma::mma_sync(fc[j], fah, fbh, fc[j]);
            wmma::mma_sync(fc[j], fah, fbl, fc[j]);
            wmma::mma_sync(fc[j], fal, fbh, fc[j]);
        }
    }
    __syncthreads();   // hs dead; os overwrites the same buffer
    #pragma unroll
    for (int j = 0; j < 4; j++)
        wmma::store_matrix_sync(&os[wm * 16 * 264 + wc + j * 16], fc[j], 264,
                                wmma::mem_row_major);
    __syncthreads();

    // epilogue: warp handles 4 nodes; lane owns 8 cols (head = lane>>3)
    float4 al0 = ((const float4*)attn_l)[lane * 2];
    float4 al1 = ((const float4*)attn_l)[lane * 2 + 1];
    float4 ar0 = ((const float4*)attn_r)[lane * 2];
    float4 ar1 = ((const float4*)attn_r)[lane * 2 + 1];
    #pragma unroll
    for (int q = 0; q < 4; q++) {
        int r = warp * 4 + q;
        int node = node0 + r;
        float4 v0 = *(float4*)&os[r * 264 + lane * 8];
        float4 v1 = *(float4*)&os[r * 264 + lane * 8 + 4];
        float pl = v0.x * al0.x + v0.y * al0.y + v0.z * al0.z + v0.w * al0.w +
                   v1.x * al1.x + v1.y * al1.y + v1.z * al1.z + v1.w * al1.w;
        float pr = v0.x * ar0.x + v0.y * ar0.y + v0.z * ar0.z + v0.w * ar0.w +
                   v1.x * ar1.x + v1.y * ar1.y + v1.z * ar1.z + v1.w * ar1.w;
        #pragma unroll
        for (int o = 4; o > 0; o >>= 1) {
            pl += __shfl_xor_sync(0xffffffffu, pl, o);
            pr += __shfl_xor_sync(0xffffffffu, pr, o);
        }
        if (node < Nn) {
            __half2 p[4];
            p[0] = __floats2half2_rn(v0.x, v0.y);
            p[1] = __floats2half2_rn(v0.z, v0.w);
            p[2] = __floats2half2_rn(v1.x, v1.y);
            p[3] = __floats2half2_rn(v1.z, v1.w);
            *(uint4*)&d_feat_h[node * 256 + lane * 8] = *(uint4*)p;
            if ((lane & 7) == 0) {
                int head = lane >> 3;
                d_el[node * 4 + head] = pl;
                d_er[node * 4 + head] = pr;
            }
        }
    }
}

// helper: split float4 into fp16 hi/lo packed as uint2
__device__ __forceinline__ void split4(float4 v, uint2& hi, uint2& lo) {
    __half h0 = __float2half_rn(v.x), h1 = __float2half_rn(v.y);
    __half h2 = __float2half_rn(v.z), h3 = __float2half_rn(v.w);
    __half2 ph[2] = {__halves2half2(h0, h1), __halves2half2(h2, h3)};
    __half2 pl[2] = {
        __halves2half2(__float2half_rn(v.x - __half2float(h0)),
                       __float2half_rn(v.y - __half2float(h1))),
        __halves2half2(__float2half_rn(v.z - __half2float(h2)),
                       __float2half_rn(v.w - __half2float(h3)))};
    hi = *(uint2*)ph;
    lo = *(uint2*)pl;
}

// ---------------- Gather: acc += w*feat, s += w; writes rst as hi/lo halves --------
__global__ void k_gather(const float* __restrict__ gat_bias) {
    int gw = (blockIdx.x * blockDim.x + threadIdx.x) >> 5;
    int lane = threadIdx.x & 31;
    if (gw >= Nn) return;
    int n = gw;
    int hA = lane >> 4;

    int beg = d_off[n], end = d_off[n + 1];
    float sA = 0.f, sB = 0.f;
    float4 aA = make_float4(0.f, 0.f, 0.f, 0.f);
    float4 aB = make_float4(0.f, 0.f, 0.f, 0.f);
    for (int i = beg; i < end; i++) {
        int sn = d_esrc[i];
        float4 w4 = d_w[i];
        float wA = hA ? w4.y : w4.x;
        float wB = hA ? w4.w : w4.z;
        sA += wA; sB += wB;
        const __half2* fp = (const __half2*)(d_feat_h + (size_t)sn * 256);
        uint2 ua = *(const uint2*)(fp + 2 * lane);
        uint2 ub = *(const uint2*)(fp + 64 + 2 * lane);
        float2 fa0 = __half22float2(*(__half2*)&ua.x);
        float2 fa1 = __half22float2(*(__half2*)&ua.y);
        float2 fb0 = __half22float2(*(__half2*)&ub.x);
        float2 fb1 = __half22float2(*(__half2*)&ub.y);
        aA.x += wA * fa0.x; aA.y += wA * fa0.y; aA.z += wA * fa1.x; aA.w += wA * fa1.y;
        aB.x += wB * fb0.x; aB.y += wB * fb0.y; aB.z += wB * fb1.x; aB.w += wB * fb1.y;
    }

    float iA = sA > 0.f ? 1.f / sA : 0.f;
    float iB = sB > 0.f ? 1.f / sB : 0.f;
    float4 bA = ((const float4*)gat_bias)[lane];
    float4 bB = ((const float4*)gat_bias)[32 + lane];
    float4 oA, oB;
    oA.x = aA.x * iA + bA.x; oA.y = aA.y * iA + bA.y;
    oA.z = aA.z * iA + bA.z; oA.w = aA.w * iA + bA.w;
    oB.x = aB.x * iB + bB.x; oB.y = aB.y * iB + bB.y;
    oB.z = aB.z * iB + bB.z; oB.w = aB.w * iB + bB.w;
    uint2 hiA, loA, hiB, loB;
    split4(oA, hiA, loA);
    split4(oB, hiB, loB);
    *(uint2*)&d_rst_hi[n * 256 + 4 * lane]       = hiA;
    *(uint2*)&d_rst_lo[n * 256 + 4 * lane]       = loA;
    *(uint2*)&d_rst_hi[n * 256 + 128 + 4 * lane] = hiB;
    *(uint2*)&d_rst_lo[n * 256 + 128 + 4 * lane] = loB;
}

// ---------------- GEMM2 + LayerNorm, fp16 split MMA ----------------
// Block 256 thr (8 warps), 32 nodes x 64 cols; 8 warp-tiles of 16x16. K=256.
__global__ void k_gemm2(const float* __restrict__ out_b,
                        const float* __restrict__ ln_g, const float* __restrict__ ln_b,
                        float* __restrict__ out) {
    __shared__ __align__(128) float sm[32 * 264];           // 33.8 KB aliased
    __half* as_hi = (__half*)sm;                             // 32 x 264 halves
    __half* as_lo = as_hi + 32 * 264;
    float* os = sm;                                          // 32 x 72 fp32 (after)
    int t = threadIdx.x;
    int lane = t & 31, warp = t >> 5;
    int node0 = blockIdx.x * 32;

    // load rst hi/lo tiles (32 nodes x 256 halves each), coalesced uint4
    #pragma unroll
    for (int i = 0; i < 4; i++) {
        int idx = t + i * 256;              // uint4 idx; 32 per node
        int row = idx >> 5, c8 = idx & 31;
        int node = node0 + row;
        uint4 vh = make_uint4(0u, 0u, 0u, 0u), vl = vh;
        if (node < Nn) {
            vh = ((const uint4*)d_rst_hi)[node * 32 + c8];
            vl = ((const uint4*)d_rst_lo)[node * 32 + c8];
        }
        *(uint4*)&as_hi[row * 264 + c8 * 8] = vh;
        *(uint4*)&as_lo[row * 264 + c8 * 8] = vl;
    }
    __syncthreads();

    int wm = warp >> 2, wn = warp & 3;

    wmma::fragment<wmma::matrix_a, 16, 16, 16, __half, wmma::row_major> fah, fal;
    wmma::fragment<wmma::matrix_b, 16, 16, 16, __half, wmma::row_major> fbh, fbl;
    wmma::fragment<wmma::accumulator, 16, 16, 16, float> fc;
    wmma::fill_fragment(fc, 0.f);

    #pragma unroll
    for (int k0 = 0; k0 < 16; k0++) {
        wmma::load_matrix_sync(fah, as_hi + wm * 16 * 264 + k0 * 16, 264);
        wmma::load_matrix_sync(fal, as_lo + wm * 16 * 264 + k0 * 16, 264);
        wmma::load_matrix_sync(fbh, d_w2hi + k0 * 16 * 64 + wn * 16, 64);
        wmma::load_matrix_sync(fbl, d_w2lo + k0 * 16 * 64 + wn * 16, 64);
        wmma::mma_sync(fc, fah, fbh, fc);
        wmma::mma_sync(fc, fah, fbl, fc);
        wmma::mma_sync(fc, fal, fbh, fc);
    }
    __syncthreads();   // A tiles dead; os overwrites buffer
    wmma::store_matrix_sync(&os[wm * 16 * 72 + wn * 16], fc, 72, wmma::mem_row_major);
    __syncthreads();

    float2 ob = ((const float2*)out_b)[lane];
    float2 g2 = ((const float2*)ln_g)[lane];
    float2 b2 = ((const float2*)ln_b)[lane];
    #pragma unroll
    for (int q = 0; q < 4; q++) {
        int r = warp * 4 + q;
        int node = node0 + r;
        float2 v = *(float2*)&os[r * 72 + lane * 2];
        float x0 = v.x + ob.x;
        float x1 = v.y + ob.y;
        float p = x0 + x1;
        float s = x0 * x0 + x1 * x1;
        #pragma unroll
        for (int o = 16; o > 0; o >>= 1) {
            p += __shfl_xor_sync(0xffffffffu, p, o);
            s += __shfl_xor_sync(0xffffffffu, s, o);
        }
        float mean = p * (1.f / 64.f);
        float var = s * (1.f / 64.f) - mean * mean;
        float rstd = rsqrtf(var + LNEPS);
        if (node < Nn) {
            float2 y;
            y.x = (x0 - mean) * rstd * g2.x + b2.x;
            y.y = (x1 - mean) * rstd * g2.y + b2.y;
            ((float2*)out)[node * 32 + lane] = y;
        }
    }
}

// ---------------- launch ----------------
extern "C" void kernel_launch(void* const* d_in, const int* in_sizes, int n_in,
                              void* d_out, int out_size) {
    const float* h        = (const float*)d_in[0];
    const int*   src      = (const int*)d_in[1];
    const int*   dst      = (const int*)d_in[2];
    const float* fc_w     = (const float*)d_in[3];
    const float* attn_l   = (const float*)d_in[4];
    const float* attn_r   = (const float*)d_in[5];
    const float* gat_bias = (const float*)d_in[6];
    const float* out_w    = (const float*)d_in[7];
    const float* out_b    = (const float*)d_in[8];
    const float* ln_g     = (const float*)d_in[9];
    const float* ln_b     = (const float*)d_in[10];
    float* out = (float*)d_out;

    k_splitw<<<(64 * 256 + 255) / 256, 256>>>(fc_w, out_w);      // 1
    k_hist<<<(Ee + 255) / 256, 256>>>(dst);                      // 2
    k_scan_part<<<SCAN_BLOCKS, 1024>>>();                        // 3
    k_gemm1<<<(Nn + 31) / 32, 256>>>(h, attn_l, attn_r);         // 4 (capture slot)
    k_scan_top<<<1, 64>>>();                                     // 5
    k_scan_final<<<SCAN_BLOCKS, 1024>>>();                       // 6
    k_scatterw<<<(Ee + 255) / 256, 256>>>(src, dst);             // 7
    k_gather<<<(Nn + 7) / 8, 256>>>(gat_bias);                   // 8
    k_gemm2<<<(Nn + 31) / 32, 256>>>(out_b, ln_g, ln_b, out);    // 9
}

// round 5
// speedup vs baseline: 2.1767x; 1.5773x over previous
#include <cuda_runtime.h>
#include <cuda_fp16.h>
#include <mma.h>
#include <math.h>

using namespace nvcuda;

#define Nn 50000
#define Ee 800000
#define NEG 0.2f
#define LNEPS 1e-5f
#define SCAN_BLOCKS ((Nn + 1023) / 1024)   // 49

// ---- scratch (static __device__ arrays: allocation is banned) ----
__device__ __half d_feat_h[Nn * 256];   // GEMM1 output as fp16 [N, H*F]
__device__ float d_el[Nn * 4];
__device__ float d_er[Nn * 4];
__device__ __half d_rst_hi[Nn * 256];   // aggregated features, fp16 hi part
__device__ __half d_rst_lo[Nn * 256];   // fp16 lo (residual) part
__device__ __half d_w1hi[64 * 256];     // fc_w split
__device__ __half d_w1lo[64 * 256];
__device__ __half d_w2hi[256 * 64];     // out_w split
__device__ __half d_w2lo[256 * 64];
__device__ uint4 d_edge[Ee];            // packed {src, w01(half2), w23(half2), pad}
__device__ int   d_cnt[Nn];             // zero-init at load; re-zeroed each call
__device__ int   d_off[Nn + 1];
__device__ int   d_cur[Nn];
__device__ int   d_bsum[SCAN_BLOCKS];
__device__ int   d_bbase[SCAN_BLOCKS];

// ---------------- weight pre-split ----------------
__global__ void k_splitw(const float* __restrict__ fc_w, const float* __restrict__ out_w) {
    int i = blockIdx.x * blockDim.x + threadIdx.x;
    if (i < 64 * 256) {
        float f1 = fc_w[i];
        __half h1 = __float2half_rn(f1);
        d_w1hi[i] = h1;
        d_w1lo[i] = __float2half_rn(f1 - __half2float(h1));
        float f2 = out_w[i];
        __half h2 = __float2half_rn(f2);
        d_w2hi[i] = h2;
        d_w2lo[i] = __float2half_rn(f2 - __half2float(h2));
    }
}

// ---------------- CSR build ----------------
__global__ void k_hist(const int* __restrict__ dst) {
    int i = blockIdx.x * blockDim.x + threadIdx.x;
    if (i < Ee) atomicAdd(&d_cnt[dst[i]], 1);
}

__global__ void k_scan_part() {
    __shared__ int wsum[32];
    int t = threadIdx.x, b = blockIdx.x;
    int lane = t & 31, wid = t >> 5;
    int i = b * 1024 + t;
    int v = (i < Nn) ? d_cnt[i] : 0;
    int x = v;
    #pragma unroll
    for (int o = 1; o < 32; o <<= 1) {
        int y = __shfl_up_sync(0xffffffffu, x, o);
        if (lane >= o) x += y;
    }
    if (lane == 31) wsum[wid] = x;
    __syncthreads();
    if (wid == 0) {
        int s = wsum[lane];
        #pragma unroll
        for (int o = 1; o < 32; o <<= 1) {
            int y = __shfl_up_sync(0xffffffffu, s, o);
            if (lane >= o) s += y;
        }
        wsum[lane] = s;
    }
    __syncthreads();
    int base = wid ? wsum[wid - 1] : 0;
    if (i < Nn) d_off[i] = base + x - v;
    if (t == 0) d_bsum[b] = wsum[31];
}

__global__ void k_scan_top() {
    int t = threadIdx.x;   // 64 threads
    int v = (t < SCAN_BLOCKS) ? d_bsum[t] : 0;
    int x = v;
    #pragma unroll
    for (int o = 1; o < 64; o <<= 1) {
        int y = __shfl_up_sync(0xffffffffu, x, o);
        if ((t & 31) >= o && o < 32) x += y;
    }
    __shared__ int w0tot;
    if (t == 31) w0tot = x;
    __syncthreads();
    if (t >= 32) x += w0tot;
    if (t < SCAN_BLOCKS) d_bbase[t] = x - v;
    if (t == SCAN_BLOCKS - 1) d_off[Nn] = x;
}

__global__ void k_scan_final() {
    int t = threadIdx.x, b = blockIdx.x;
    int i = b * 1024 + t;
    if (i < Nn) {
        int off = d_off[i] + d_bbase[b];
        d_off[i] = off;
        d_cur[i] = off;
        d_cnt[i] = 0;
    }
}

// scatter + per-edge softmax weight, packed 16B record
__global__ void k_scatterw(const int* __restrict__ src, const int* __restrict__ dst) {
    int i = blockIdx.x * blockDim.x + threadIdx.x;
    if (i >= Ee) return;
    int s = src[i], d = dst[i];
    float4 el4 = ((const float4*)d_el)[s];
    float4 er4 = ((const float4*)d_er)[d];
    float e0 = el4.x + er4.x; e0 = e0 > 0.f ? e0 : NEG * e0;
    float e1 = el4.y + er4.y; e1 = e1 > 0.f ? e1 : NEG * e1;
    float e2 = el4.z + er4.z; e2 = e2 > 0.f ? e2 : NEG * e2;
    float e3 = el4.w + er4.w; e3 = e3 > 0.f ? e3 : NEG * e3;
    // logits small (|e| < ~8): exp in [3e-4, 3e3], fits fp16; skip max-subtraction
    __half2 w01 = __floats2half2_rn(__expf(e0), __expf(e1));
    __half2 w23 = __floats2half2_rn(__expf(e2), __expf(e3));
    int p = atomicAdd(&d_cur[d], 1);
    uint4 rec;
    rec.x = (unsigned)s;
    rec.y = *(unsigned*)&w01;
    rec.z = *(unsigned*)&w23;
    rec.w = 0u;
    d_edge[p] = rec;
}

// ---------------- GEMM1: feat = h @ fc_w, fp16 split MMA, B staged via shared ------
// Block 256 thr (8 warps), 64 nodes x 256 cols; warp = 32 rows x 64 cols.
__global__ void k_gemm1(const float* __restrict__ h,
                        const float* __restrict__ attn_l, const float* __restrict__ attn_r) {
    __shared__ __align__(128) __half smh[17664];   // 35.3 KB, aliased
    __half* ah = smh;                 // 64 x 72
    __half* al = ah + 4608;
    __half* bh = al + 4608;           // 16 x 264 (one K-chunk of fc_w)
    __half* bl = bh + 4224;
    float* os = (float*)smh;          // 32 x 264 fp32 staging (per phase)
    int t = threadIdx.x;
    int lane = t & 31, warp = t >> 5;
    int node0 = blockIdx.x * 64;

    // load h tile (64 nodes x 64), split fp32 -> fp16 hi/lo
    #pragma unroll
    for (int i = 0; i < 4; i++) {
        int idx = t + i * 256;              // float4 idx; 16 per node
        int row = idx >> 4, c4 = idx & 15;
        float4 v = make_float4(0.f, 0.f, 0.f, 0.f);
        int node = node0 + row;
        if (node < Nn) v = ((const float4*)h)[node * 16 + c4];
        __half h0 = __float2half_rn(v.x), h1 = __float2half_rn(v.y);
        __half h2 = __float2half_rn(v.z), h3 = __float2half_rn(v.w);
        __half2 ph[2] = {__halves2half2(h0, h1), __halves2half2(h2, h3)};
        __half2 pl[2] = {
            __halves2half2(__float2half_rn(v.x - __half2float(h0)),
                           __float2half_rn(v.y - __half2float(h1))),
            __halves2half2(__float2half_rn(v.z - __half2float(h2)),
                           __float2half_rn(v.w - __half2float(h3)))};
        *(uint2*)&ah[row * 72 + c4 * 4] = *(uint2*)ph;
        *(uint2*)&al[row * 72 + c4 * 4] = *(uint2*)pl;
    }

    int wm = warp >> 2, wn = warp & 3;   // wm: 32-row slab, wn: 64-col slab

    wmma::fragment<wmma::matrix_a, 16, 16, 16, __half, wmma::row_major> fah, fal;
    wmma::fragment<wmma::matrix_b, 16, 16, 16, __half, wmma::row_major> fbh, fbl;
    wmma::fragment<wmma::accumulator, 16, 16, 16, float> acc[2][4];
    #pragma unroll
    for (int m = 0; m < 2; m++)
        #pragma unroll
        for (int j = 0; j < 4; j++) wmma::fill_fragment(acc[m][j], 0.f);

    for (int k0 = 0; k0 < 4; k0++) {
        __syncthreads();   // prior compute done (and A stores visible on k0=0)
        // stage B chunk rows [k0*16, k0*16+16) coalesced
        #pragma unroll
        for (int i = 0; i < 2; i++) {
            int idx = t + i * 256;          // uint4 idx over 16x32
            int row = idx >> 5, c8 = idx & 31;
            *(uint4*)&bh[row * 264 + c8 * 8] =
                ((const uint4*)d_w1hi)[(k0 * 16 + row) * 32 + c8];
            *(uint4*)&bl[row * 264 + c8 * 8] =
                ((const uint4*)d_w1lo)[(k0 * 16 + row) * 32 + c8];
        }
        __syncthreads();
        #pragma unroll
        for (int m = 0; m < 2; m++) {
            wmma::load_matrix_sync(fah, ah + (wm * 32 + m * 16) * 72 + k0 * 16, 72);
            wmma::load_matrix_sync(fal, al + (wm * 32 + m * 16) * 72 + k0 * 16, 72);
            #pragma unroll
            for (int j = 0; j < 4; j++) {
                wmma::load_matrix_sync(fbh, bh + wn * 64 + j * 16, 264);
                wmma::load_matrix_sync(fbl, bl + wn * 64 + j * 16, 264);
                wmma::mma_sync(acc[m][j], fah, fbh, acc[m][j]);
                wmma::mma_sync(acc[m][j], fah, fbl, acc[m][j]);
                wmma::mma_sync(acc[m][j], fal, fbh, acc[m][j]);
            }
        }
    }
    __syncthreads();   // operands dead; os overwrites

    float4 al0 = ((const float4*)attn_l)[lane * 2];
    float4 al1 = ((const float4*)attn_l)[lane * 2 + 1];
    float4 ar0 = ((const float4*)attn_r)[lane * 2];
    float4 ar1 = ((const float4*)attn_r)[lane * 2 + 1];

    #pragma unroll
    for (int phase = 0; phase < 2; phase++) {
        if (wm == phase) {
            #pragma unroll
            for (int m = 0; m < 2; m++)
                #pragma unroll
                for (int j = 0; j < 4; j++)
                    wmma::store_matrix_sync(&os[(m * 16) * 264 + wn * 64 + j * 16],
                                            acc[m][j], 264, wmma::mem_row_major);
        }
        __syncthreads();
        // epilogue on 32 rows; each warp handles 4
        #pragma unroll
        for (int q = 0; q < 4; q++) {
            int r = warp * 4 + q;
            int node = node0 + phase * 32 + r;
            float4 v0 = *(float4*)&os[r * 264 + lane * 8];
            float4 v1 = *(float4*)&os[r * 264 + lane * 8 + 4];
            float pl = v0.x * al0.x + v0.y * al0.y + v0.z * al0.z + v0.w * al0.w +
                       v1.x * al1.x + v1.y * al1.y + v1.z * al1.z + v1.w * al1.w;
            float pr = v0.x * ar0.x + v0.y * ar0.y + v0.z * ar0.z + v0.w * ar0.w +
                       v1.x * ar1.x + v1.y * ar1.y + v1.z * ar1.z + v1.w * ar1.w;
            #pragma unroll
            for (int o = 4; o > 0; o >>= 1) {
                pl += __shfl_xor_sync(0xffffffffu, pl, o);
                pr += __shfl_xor_sync(0xffffffffu, pr, o);
            }
            if (node < Nn) {
                __half2 p[4];
                p[0] = __floats2half2_rn(v0.x, v0.y);
                p[1] = __floats2half2_rn(v0.z, v0.w);
                p[2] = __floats2half2_rn(v1.x, v1.y);
                p[3] = __floats2half2_rn(v1.z, v1.w);
                *(uint4*)&d_feat_h[node * 256 + lane * 8] = *(uint4*)p;
                if ((lane & 7) == 0) {
                    int head = lane >> 3;
                    d_el[node * 4 + head] = pl;
                    d_er[node * 4 + head] = pr;
                }
            }
        }
        __syncthreads();
    }
}

// helper: split float4 into fp16 hi/lo packed as uint2
__device__ __forceinline__ void split4(float4 v, uint2& hi, uint2& lo) {
    __half h0 = __float2half_rn(v.x), h1 = __float2half_rn(v.y);
    __half h2 = __float2half_rn(v.z), h3 = __float2half_rn(v.w);
    __half2 ph[2] = {__halves2half2(h0, h1), __halves2half2(h2, h3)};
    __half2 pl[2] = {
        __halves2half2(__float2half_rn(v.x - __half2float(h0)),
                       __float2half_rn(v.y - __half2float(h1))),
        __halves2half2(__float2half_rn(v.z - __half2float(h2)),
                       __float2half_rn(v.w - __half2float(h3)))};
    hi = *(uint2*)ph;
    lo = *(uint2*)pl;
}

// ---------------- Gather: acc += w*feat, s += w; writes rst hi/lo (warp/dst) --------
__global__ void k_gather(const float* __restrict__ gat_bias) {
    int gw = (blockIdx.x * blockDim.x + threadIdx.x) >> 5;
    int lane = threadIdx.x & 31;
    if (gw >= Nn) return;
    int n = gw;
    int hA = lane >> 4;

    int beg = d_off[n], end = d_off[n + 1];
    float sA = 0.f, sB = 0.f;
    float4 aA = make_float4(0.f, 0.f, 0.f, 0.f);
    float4 aB = make_float4(0.f, 0.f, 0.f, 0.f);
    for (int i = beg; i < end; i++) {
        uint4 rec = d_edge[i];
        int sn = (int)rec.x;
        float2 w01 = __half22float2(*(__half2*)&rec.y);
        float2 w23 = __half22float2(*(__half2*)&rec.z);
        float wA = hA ? w01.y : w01.x;
        float wB = hA ? w23.y : w23.x;
        sA += wA; sB += wB;
        const __half2* fp = (const __half2*)(d_feat_h + (size_t)sn * 256);
        uint2 ua = *(const uint2*)(fp + 2 * lane);
        uint2 ub = *(const uint2*)(fp + 64 + 2 * lane);
        float2 fa0 = __half22float2(*(__half2*)&ua.x);
        float2 fa1 = __half22float2(*(__half2*)&ua.y);
        float2 fb0 = __half22float2(*(__half2*)&ub.x);
        float2 fb1 = __half22float2(*(__half2*)&ub.y);
        aA.x += wA * fa0.x; aA.y += wA * fa0.y; aA.z += wA * fa1.x; aA.w += wA * fa1.y;
        aB.x += wB * fb0.x; aB.y += wB * fb0.y; aB.z += wB * fb1.x; aB.w += wB * fb1.y;
    }

    float iA = sA > 0.f ? 1.f / sA : 0.f;
    float iB = sB > 0.f ? 1.f / sB : 0.f;
    float4 bA = ((const float4*)gat_bias)[lane];
    float4 bB = ((const float4*)gat_bias)[32 + lane];
    float4 oA, oB;
    oA.x = aA.x * iA + bA.x; oA.y = aA.y * iA + bA.y;
    oA.z = aA.z * iA + bA.z; oA.w = aA.w * iA + bA.w;
    oB.x = aB.x * iB + bB.x; oB.y = aB.y * iB + bB.y;
    oB.z = aB.z * iB + bB.z; oB.w = aB.w * iB + bB.w;
    uint2 hiA, loA, hiB, loB;
    split4(oA, hiA, loA);
    split4(oB, hiB, loB);
    *(uint2*)&d_rst_hi[n * 256 + 4 * lane]       = hiA;
    *(uint2*)&d_rst_lo[n * 256 + 4 * lane]       = loA;
    *(uint2*)&d_rst_hi[n * 256 + 128 + 4 * lane] = hiB;
    *(uint2*)&d_rst_lo[n * 256 + 128 + 4 * lane] = loB;
}

// ---------------- GEMM2 + LayerNorm, fp16 split MMA, operands staged via shared ------
// Block 256 thr (8 warps), 64 nodes x 64 cols; warp = 32 rows x 16 cols. K=256.
__global__ void k_gemm2(const float* __restrict__ out_b,
                        const float* __restrict__ ln_g, const float* __restrict__ ln_b,
                        float* __restrict__ out) {
    __shared__ __align__(128) __half smh[18432];   // 36.9 KB, aliased
    __half* ah = smh;                 // 64 x 72 (A K-chunk)
    __half* al = ah + 4608;
    __half* bh = al + 4608;           // 64 x 72 (B K-chunk)
    __half* bl = bh + 4608;
    float* os = (float*)smh;          // 64 x 72 fp32 staging
    int t = threadIdx.x;
    int lane = t & 31, warp = t >> 5;
    int node0 = blockIdx.x * 64;

    int wm = warp >> 2, wn = warp & 3;

    wmma::fragment<wmma::matrix_a, 16, 16, 16, __half, wmma::row_major> fah, fal;
    wmma::fragment<wmma::matrix_b, 16, 16, 16, __half, wmma::row_major> fbh, fbl;
    wmma::fragment<wmma::accumulator, 16, 16, 16, float> acc[2];
    wmma::fill_fragment(acc[0], 0.f);
    wmma::fill_fragment(acc[1], 0.f);

    for (int kc = 0; kc < 4; kc++) {
        __syncthreads();
        // stage A chunk (64 nodes x 64 halves) hi/lo, coalesced uint4
        #pragma unroll
        for (int i = 0; i < 2; i++) {
            int idx = t + i * 256;          // uint4 idx over 64x8
            int row = idx >> 3, c8 = idx & 7;
            int node = node0 + row;
            uint4 vh = make_uint4(0u, 0u, 0u, 0u), vl = vh;
            if (node < Nn) {
                vh = ((const uint4*)d_rst_hi)[node * 32 + kc * 8 + c8];
                vl = ((const uint4*)d_rst_lo)[node * 32 + kc * 8 + c8];
            }
            *(uint4*)&ah[row * 72 + c8 * 8] = vh;
            *(uint4*)&al[row * 72 + c8 * 8] = vl;
        }
        // stage B chunk (64 k-rows x 64 cols) hi/lo
        #pragma unroll
        for (int i = 0; i < 2; i++) {
            int idx = t + i * 256;
            int row = idx >> 3, c8 = idx & 7;
            *(uint4*)&bh[row * 72 + c8 * 8] =
                ((const uint4*)d_w2hi)[(kc * 64 + row) * 8 + c8];
            *(uint4*)&bl[row * 72 + c8 * 8] =
                ((const uint4*)d_w2lo)[(kc * 64 + row) * 8 + c8];
        }
        __syncthreads();
        #pragma unroll
        for (int k1 = 0; k1 < 4; k1++) {
            wmma::load_matrix_sync(fbh, bh + k1 * 16 * 72 + wn * 16, 72);
            wmma::load_matrix_sync(fbl, bl + k1 * 16 * 72 + wn * 16, 72);
            #pragma unroll
            for (int m = 0; m < 2; m++) {
                wmma::load_matrix_sync(fah, ah + (wm * 32 + m * 16) * 72 + k1 * 16, 72);
                wmma::load_matrix_sync(fal, al + (wm * 32 + m * 16) * 72 + k1 * 16, 72);
                wmma::mma_sync(acc[m], fah, fbh, acc[m]);
                wmma::mma_sync(acc[m], fah, fbl, acc[m]);
                wmma::mma_sync(acc[m], fal, fbh, acc[m]);
            }
        }
    }
    __syncthreads();   // operands dead; os overwrites
    #pragma unroll
    for (int m = 0; m < 2; m++)
        wmma::store_matrix_sync(&os[(wm * 32 + m * 16) * 72 + wn * 16], acc[m], 72,
                                wmma::mem_row_major);
    __syncthreads();

    // LayerNorm epilogue: warp handles 8 rows; lane owns cols {2l, 2l+1}
    float2 ob = ((const float2*)out_b)[lane];
    float2 g2 = ((const float2*)ln_g)[lane];
    float2 b2 = ((const float2*)ln_b)[lane];
    #pragma unroll
    for (int q = 0; q < 8; q++) {
        int r = warp * 8 + q;
        int node = node0 + r;
        float2 v = *(float2*)&os[r * 72 + lane * 2];
        float x0 = v.x + ob.x;
        float x1 = v.y + ob.y;
        float p = x0 + x1;
        float s = x0 * x0 + x1 * x1;
        #pragma unroll
        for (int o = 16; o > 0; o >>= 1) {
            p += __shfl_xor_sync(0xffffffffu, p, o);
            s += __shfl_xor_sync(0xffffffffu, s, o);
        }
        float mean = p * (1.f / 64.f);
        float var = s * (1.f / 64.f) - mean * mean;
        float rstd = rsqrtf(var + LNEPS);
        if (node < Nn) {
            float2 y;
            y.x = (x0 - mean) * rstd * g2.x + b2.x;
            y.y = (x1 - mean) * rstd * g2.y + b2.y;
            ((float2*)out)[node * 32 + lane] = y;
        }
    }
}

// ---------------- launch ----------------
extern "C" void kernel_launch(void* const* d_in, const int* in_sizes, int n_in,
                              void* d_out, int out_size) {
    const float* h        = (const float*)d_in[0];
    const int*   src      = (const int*)d_in[1];
    const int*   dst      = (const int*)d_in[2];
    const float* fc_w     = (const float*)d_in[3];
    const float* attn_l   = (const float*)d_in[4];
    const float* attn_r   = (const float*)d_in[5];
    const float* gat_bias = (const float*)d_in[6];
    const float* out_w    = (const float*)d_in[7];
    const float* out_b    = (const float*)d_in[8];
    const float* ln_g     = (const float*)d_in[9];
    const float* ln_b     = (const float*)d_in[10];
    float* out = (float*)d_out;

    k_splitw<<<(64 * 256 + 255) / 256, 256>>>(fc_w, out_w);      // 1
    k_hist<<<(Ee + 255) / 256, 256>>>(dst);                      // 2
    k_scan_part<<<SCAN_BLOCKS, 1024>>>();                        // 3
    k_gemm1<<<(Nn + 63) / 64, 256>>>(h, attn_l, attn_r);         // 4 (capture slot)
    k_scan_top<<<1, 64>>>();                                     // 5
    k_scan_final<<<SCAN_BLOCKS, 1024>>>();                       // 6
    k_scatterw<<<(Ee + 255) / 256, 256>>>(src, dst);             // 7
    k_gather<<<(Nn + 7) / 8, 256>>>(gat_bias);                   // 8
    k_gemm2<<<(Nn + 63) / 64, 256>>>(out_b, ln_g, ln_b, out);    // 9
}

// round 6
// speedup vs baseline: 2.3483x; 1.0788x over previous
#include <cuda_runtime.h>
#include <cuda_fp16.h>
#include <cuda_pipeline.h>
#include <mma.h>
#include <math.h>

using namespace nvcuda;

#define Nn 50000
#define Ee 800000
#define NEG 0.2f
#define LNEPS 1e-5f
#define SCAN_BLOCKS ((Nn + 1023) / 1024)   // 49

// ---- scratch (static __device__ arrays: allocation is banned) ----
__device__ __half d_feat_h[Nn * 256];   // GEMM1 output as fp16 [N, H*F]
__device__ float d_el[Nn * 4];
__device__ float d_er[Nn * 4];
__device__ __half d_rst_hi[Nn * 256];   // aggregated features, fp16 hi part
__device__ __half d_rst_lo[Nn * 256];   // fp16 lo (residual) part
__device__ __half d_w1hi[64 * 256];     // fc_w split
__device__ __half d_w1lo[64 * 256];
__device__ __half d_w2hi[256 * 64];     // out_w split
__device__ __half d_w2lo[256 * 64];
__device__ uint4 d_edge[Ee];            // packed {src, w01(half2), w23(half2), pad}
__device__ int   d_cnt[Nn];             // zero-init at load; re-zeroed each call
__device__ int   d_off[Nn + 1];
__device__ int   d_cur[Nn];
__device__ int   d_bsum[SCAN_BLOCKS];

// ---------------- hist + weight pre-split (fused) ----------------
__global__ void k_hist_split(const int* __restrict__ dst,
                             const float* __restrict__ fc_w,
                             const float* __restrict__ out_w) {
    int i = blockIdx.x * blockDim.x + threadIdx.x;
    if (i < 64 * 256) {
        float f1 = fc_w[i];
        __half h1 = __float2half_rn(f1);
        d_w1hi[i] = h1;
        d_w1lo[i] = __float2half_rn(f1 - __half2float(h1));
        float f2 = out_w[i];
        __half h2 = __float2half_rn(f2);
        d_w2hi[i] = h2;
        d_w2lo[i] = __float2half_rn(f2 - __half2float(h2));
    }
    if (i < Ee) atomicAdd(&d_cnt[dst[i]], 1);
}

__global__ void k_scan_part() {
    __shared__ int wsum[32];
    int t = threadIdx.x, b = blockIdx.x;
    int lane = t & 31, wid = t >> 5;
    int i = b * 1024 + t;
    int v = (i < Nn) ? d_cnt[i] : 0;
    int x = v;
    #pragma unroll
    for (int o = 1; o < 32; o <<= 1) {
        int y = __shfl_up_sync(0xffffffffu, x, o);
        if (lane >= o) x += y;
    }
    if (lane == 31) wsum[wid] = x;
    __syncthreads();
    if (wid == 0) {
        int s = wsum[lane];
        #pragma unroll
        for (int o = 1; o < 32; o <<= 1) {
            int y = __shfl_up_sync(0xffffffffu, s, o);
            if (lane >= o) s += y;
        }
        wsum[lane] = s;
    }
    __syncthreads();
    int base = wid ? wsum[wid - 1] : 0;
    if (i < Nn) d_off[i] = base + x - v;
    if (t == 0) d_bsum[b] = wsum[31];
}

// fold of scan_top + scan_final: each block reduces its base from d_bsum
__global__ void k_scan_final2() {
    __shared__ int sbase;
    int t = threadIdx.x, b = blockIdx.x;
    if (t < 32) {
        int v = 0;
        for (int j = t; j < b; j += 32) v += d_bsum[j];
        #pragma unroll
        for (int o = 16; o > 0; o >>= 1) v += __shfl_xor_sync(0xffffffffu, v, o);
        if (t == 0) sbase = v;
    }
    __syncthreads();
    int i = b * 1024 + t;
    if (i < Nn) {
        int c = d_cnt[i];
        int off = d_off[i] + sbase;
        d_off[i] = off;
        d_cur[i] = off;
        d_cnt[i] = 0;
        if (i == Nn - 1) d_off[Nn] = off + c;
    }
}

// scatter + per-edge softmax weight, packed 16B record
__global__ void k_scatterw(const int* __restrict__ src, const int* __restrict__ dst) {
    int i = blockIdx.x * blockDim.x + threadIdx.x;
    if (i >= Ee) return;
    int s = src[i], d = dst[i];
    float4 el4 = ((const float4*)d_el)[s];
    float4 er4 = ((const float4*)d_er)[d];
    float e0 = el4.x + er4.x; e0 = e0 > 0.f ? e0 : NEG * e0;
    float e1 = el4.y + er4.y; e1 = e1 > 0.f ? e1 : NEG * e1;
    float e2 = el4.z + er4.z; e2 = e2 > 0.f ? e2 : NEG * e2;
    float e3 = el4.w + er4.w; e3 = e3 > 0.f ? e3 : NEG * e3;
    // logits small (|e| < ~8): exp in [3e-4, 3e3], fits fp16; skip max-subtraction
    __half2 w01 = __floats2half2_rn(__expf(e0), __expf(e1));
    __half2 w23 = __floats2half2_rn(__expf(e2), __expf(e3));
    int p = atomicAdd(&d_cur[d], 1);
    uint4 rec;
    rec.x = (unsigned)s;
    rec.y = *(unsigned*)&w01;
    rec.z = *(unsigned*)&w23;
    rec.w = 0u;
    d_edge[p] = rec;
}

// ---------------- GEMM1: feat = h @ fc_w, fp16 split MMA, cp.async B pipeline ----
// Dynamic smem layout (halves): ah[64*72], al[64*72], then 2 B buffers of
// {bh[16*264], bl[16*264]}. fp32 out staging (32x264) aliases the whole region.
__global__ void k_gemm1(const float* __restrict__ h,
                        const float* __restrict__ attn_l, const float* __restrict__ attn_r) {
    extern __shared__ __align__(128) __half dyn[];
    __half* ah = dyn;                    // 64 x 72
    __half* al = ah + 4608;
    float* os = (float*)dyn;             // 32 x 264 fp32 staging (per phase)
    int t = threadIdx.x;
    int lane = t & 31, warp = t >> 5;
    int node0 = blockIdx.x * 64;

    // load h tile (64 nodes x 64), split fp32 -> fp16 hi/lo
    #pragma unroll
    for (int i = 0; i < 4; i++) {
        int idx = t + i * 256;              // float4 idx; 16 per node
        int row = idx >> 4, c4 = idx & 15;
        float4 v = make_float4(0.f, 0.f, 0.f, 0.f);
        int node = node0 + row;
        if (node < Nn) v = ((const float4*)h)[node * 16 + c4];
        __half h0 = __float2half_rn(v.x), h1 = __float2half_rn(v.y);
        __half h2 = __float2half_rn(v.z), h3 = __float2half_rn(v.w);
        __half2 ph[2] = {__halves2half2(h0, h1), __halves2half2(h2, h3)};
        __half2 pl[2] = {
            __halves2half2(__float2half_rn(v.x - __half2float(h0)),
                           __float2half_rn(v.y - __half2float(h1))),
            __halves2half2(__float2half_rn(v.z - __half2float(h2)),
                           __float2half_rn(v.w - __half2float(h3)))};
        *(uint2*)&ah[row * 72 + c4 * 4] = *(uint2*)ph;
        *(uint2*)&al[row * 72 + c4 * 4] = *(uint2*)pl;
    }

    // async stage of B chunk k into buffer q
    auto stage_b = [&](int k, int q) {
        __half* bh = dyn + 9216 + q * 8448;
        __half* bl = bh + 4224;
        #pragma unroll
        for (int i = 0; i < 2; i++) {
            int idx = t + i * 256;          // uint4 idx over 16x32
            int row = idx >> 5, c8 = idx & 31;
            __pipeline_memcpy_async(&bh[row * 264 + c8 * 8],
                                    &((const uint4*)d_w1hi)[(k * 16 + row) * 32 + c8], 16);
            __pipeline_memcpy_async(&bl[row * 264 + c8 * 8],
                                    &((const uint4*)d_w1lo)[(k * 16 + row) * 32 + c8], 16);
        }
        __pipeline_commit();
    };
    stage_b(0, 0);

    int wm = warp >> 2, wn = warp & 3;   // wm: 32-row slab, wn: 64-col slab

    wmma::fragment<wmma::matrix_a, 16, 16, 16, __half, wmma::row_major> fah, fal;
    wmma::fragment<wmma::matrix_b, 16, 16, 16, __half, wmma::row_major> fbh, fbl;
    wmma::fragment<wmma::accumulator, 16, 16, 16, float> acc[2][4];
    #pragma unroll
    for (int m = 0; m < 2; m++)
        #pragma unroll
        for (int j = 0; j < 4; j++) wmma::fill_fragment(acc[m][j], 0.f);

    for (int k0 = 0; k0 < 4; k0++) {
        __syncthreads();   // prior compute done (k0=0: A stores ordering point)
        if (k0 < 3) {
            stage_b(k0 + 1, (k0 + 1) & 1);
            __pipeline_wait_prior(1);
        } else {
            __pipeline_wait_prior(0);
        }
        __syncthreads();   // chunk k0 copies visible to all
        __half* bh = dyn + 9216 + (k0 & 1) * 8448;
        __half* bl = bh + 4224;
        #pragma unroll
        for (int m = 0; m < 2; m++) {
            wmma::load_matrix_sync(fah, ah + (wm * 32 + m * 16) * 72 + k0 * 16, 72);
            wmma::load_matrix_sync(fal, al + (wm * 32 + m * 16) * 72 + k0 * 16, 72);
            #pragma unroll
            for (int j = 0; j < 4; j++) {
                wmma::load_matrix_sync(fbh, bh + wn * 64 + j * 16, 264);
                wmma::load_matrix_sync(fbl, bl + wn * 64 + j * 16, 264);
                wmma::mma_sync(acc[m][j], fah, fbh, acc[m][j]);
                wmma::mma_sync(acc[m][j], fah, fbl, acc[m][j]);
                wmma::mma_sync(acc[m][j], fal, fbh, acc[m][j]);
            }
        }
    }
    __syncthreads();   // operands dead; os overwrites

    float4 al0 = ((const float4*)attn_l)[lane * 2];
    float4 al1 = ((const float4*)attn_l)[lane * 2 + 1];
    float4 ar0 = ((const float4*)attn_r)[lane * 2];
    float4 ar1 = ((const float4*)attn_r)[lane * 2 + 1];

    #pragma unroll
    for (int phase = 0; phase < 2; phase++) {
        if (wm == phase) {
            #pragma unroll
            for (int m = 0; m < 2; m++)
                #pragma unroll
                for (int j = 0; j < 4; j++)
                    wmma::store_matrix_sync(&os[(m * 16) * 264 + wn * 64 + j * 16],
                                            acc[m][j], 264, wmma::mem_row_major);
        }
        __syncthreads();
        #pragma unroll
        for (int q = 0; q < 4; q++) {
            int r = warp * 4 + q;
            int node = node0 + phase * 32 + r;
            float4 v0 = *(float4*)&os[r * 264 + lane * 8];
            float4 v1 = *(float4*)&os[r * 264 + lane * 8 + 4];
            float pl = v0.x * al0.x + v0.y * al0.y + v0.z * al0.z + v0.w * al0.w +
                       v1.x * al1.x + v1.y * al1.y + v1.z * al1.z + v1.w * al1.w;
            float pr = v0.x * ar0.x + v0.y * ar0.y + v0.z * ar0.z + v0.w * ar0.w +
                       v1.x * ar1.x + v1.y * ar1.y + v1.z * ar1.z + v1.w * ar1.w;
            #pragma unroll
            for (int o = 4; o > 0; o >>= 1) {
                pl += __shfl_xor_sync(0xffffffffu, pl, o);
                pr += __shfl_xor_sync(0xffffffffu, pr, o);
            }
            if (node < Nn) {
                __half2 p[4];
                p[0] = __floats2half2_rn(v0.x, v0.y);
                p[1] = __floats2half2_rn(v0.z, v0.w);
                p[2] = __floats2half2_rn(v1.x, v1.y);
                p[3] = __floats2half2_rn(v1.z, v1.w);
                *(uint4*)&d_feat_h[node * 256 + lane * 8] = *(uint4*)p;
                if ((lane & 7) == 0) {
                    int head = lane >> 3;
                    d_el[node * 4 + head] = pl;
                    d_er[node * 4 + head] = pr;
                }
            }
        }
        __syncthreads();
    }
}

// helper: accumulate 8 halves (uint4) scaled by w into a[8]
__device__ __forceinline__ void acc8(float* a, uint4 f, float w) {
    float2 p0 = __half22float2(*(__half2*)&f.x);
    float2 p1 = __half22float2(*(__half2*)&f.y);
    float2 p2 = __half22float2(*(__half2*)&f.z);
    float2 p3 = __half22float2(*(__half2*)&f.w);
    a[0] += w * p0.x; a[1] += w * p0.y;
    a[2] += w * p1.x; a[3] += w * p1.y;
    a[4] += w * p2.x; a[5] += w * p2.y;
    a[6] += w * p3.x; a[7] += w * p3.y;
}

// ---------------- Gather: lane owns 8 consecutive cols (head = lane>>3) ------------
__global__ void k_gather(const float* __restrict__ gat_bias) {
    int gw = (blockIdx.x * blockDim.x + threadIdx.x) >> 5;
    int lane = threadIdx.x & 31;
    if (gw >= Nn) return;
    int n = gw;
    int head = lane >> 3;

    int beg = d_off[n], end = d_off[n + 1];
    float s = 0.f;
    float a[8] = {0.f, 0.f, 0.f, 0.f, 0.f, 0.f, 0.f, 0.f};

    int i = beg;
    for (; i + 2 <= end; i += 2) {
        uint4 r0 = d_edge[i];
        uint4 r1 = d_edge[i + 1];
        uint4 f0 = *(const uint4*)&d_feat_h[(size_t)r0.x * 256 + lane * 8];
        uint4 f1 = *(const uint4*)&d_feat_h[(size_t)r1.x * 256 + lane * 8];
        float w0 = __half2float(((const __half*)&r0.y)[head]);
        float w1 = __half2float(((const __half*)&r1.y)[head]);
        s += w0 + w1;
        acc8(a, f0, w0);
        acc8(a, f1, w1);
    }
    if (i < end) {
        uint4 r0 = d_edge[i];
        uint4 f0 = *(const uint4*)&d_feat_h[(size_t)r0.x * 256 + lane * 8];
        float w0 = __half2float(((const __half*)&r0.y)[head]);
        s += w0;
        acc8(a, f0, w0);
    }

    float inv = s > 0.f ? 1.f / s : 0.f;
    float4 b0 = ((const float4*)gat_bias)[lane * 2];
    float4 b1 = ((const float4*)gat_bias)[lane * 2 + 1];
    float o[8];
    o[0] = a[0] * inv + b0.x; o[1] = a[1] * inv + b0.y;
    o[2] = a[2] * inv + b0.z; o[3] = a[3] * inv + b0.w;
    o[4] = a[4] * inv + b1.x; o[5] = a[5] * inv + b1.y;
    o[6] = a[6] * inv + b1.z; o[7] = a[7] * inv + b1.w;

    __half2 hi[4], lo[4];
    #pragma unroll
    for (int j = 0; j < 4; j++) {
        __half h0 = __float2half_rn(o[2 * j]), h1 = __float2half_rn(o[2 * j + 1]);
        hi[j] = __halves2half2(h0, h1);
        lo[j] = __halves2half2(__float2half_rn(o[2 * j] - __half2float(h0)),
                               __float2half_rn(o[2 * j + 1] - __half2float(h1)));
    }
    *(uint4*)&d_rst_hi[n * 256 + lane * 8] = *(uint4*)hi;
    *(uint4*)&d_rst_lo[n * 256 + lane * 8] = *(uint4*)lo;
}

// ---------------- GEMM2 + LayerNorm, fp16 split MMA, cp.async A+B pipeline ----------
// Dynamic smem: 2 buffers of {ah,al,bh,bl}[64*72] each; fp32 staging aliases.
__global__ void k_gemm2(const float* __restrict__ out_b,
                        const float* __restrict__ ln_g, const float* __restrict__ ln_b,
                        float* __restrict__ out) {
    extern __shared__ __align__(128) __half dyn[];
    float* os = (float*)dyn;          // 64 x 72 fp32 staging
    int t = threadIdx.x;
    int lane = t & 31, warp = t >> 5;
    int node0 = blockIdx.x * 64;

    auto stage_ab = [&](int kc, int q) {
        __half* base = dyn + q * 18432;
        __half* ah = base;
        __half* al = base + 4608;
        __half* bh = base + 9216;
        __half* bl = base + 13824;
        #pragma unroll
        for (int i = 0; i < 2; i++) {
            int idx = t + i * 256;          // uint4 idx over 64x8
            int row = idx >> 3, c8 = idx & 7;
            int node = node0 + row;
            int nn = node < Nn ? node : 0;
            size_t zf = node < Nn ? 0 : 16;
            __pipeline_memcpy_async(&ah[row * 72 + c8 * 8],
                                    &((const uint4*)d_rst_hi)[nn * 32 + kc * 8 + c8], 16, zf);
            __pipeline_memcpy_async(&al[row * 72 + c8 * 8],
                                    &((const uint4*)d_rst_lo)[nn * 32 + kc * 8 + c8], 16, zf);
            __pipeline_memcpy_async(&bh[row * 72 + c8 * 8],
                                    &((const uint4*)d_w2hi)[(kc * 64 + row) * 8 + c8], 16);
            __pipeline_memcpy_async(&bl[row * 72 + c8 * 8],
                                    &((const uint4*)d_w2lo)[(kc * 64 + row) * 8 + c8], 16);
        }
        __pipeline_commit();
    };
    stage_ab(0, 0);

    int wm = warp >> 2, wn = warp & 3;

    wmma::fragment<wmma::matrix_a, 16, 16, 16, __half, wmma::row_major> fah, fal;
    wmma::fragment<wmma::matrix_b, 16, 16, 16, __half, wmma::row_major> fbh, fbl;
    wmma::fragment<wmma::accumulator, 16, 16, 16, float> acc[2];
    wmma::fill_fragment(acc[0], 0.f);
    wmma::fill_fragment(acc[1], 0.f);

    for (int kc = 0; kc < 4; kc++) {
        __syncthreads();   // prior compute done before overwriting old buffer
        if (kc < 3) {
            stage_ab(kc + 1, (kc + 1) & 1);
            __pipeline_wait_prior(1);
        } else {
            __pipeline_wait_prior(0);
        }
        __syncthreads();   // chunk kc copies visible
        __half* base = dyn + (kc & 1) * 18432;
        __half* ah = base;
        __half* al = base + 4608;
        __half* bh = base + 9216;
        __half* bl = base + 13824;
        #pragma unroll
        for (int k1 = 0; k1 < 4; k1++) {
            wmma::load_matrix_sync(fbh, bh + k1 * 16 * 72 + wn * 16, 72);
            wmma::load_matrix_sync(fbl, bl + k1 * 16 * 72 + wn * 16, 72);
            #pragma unroll
            for (int m = 0; m < 2; m++) {
                wmma::load_matrix_sync(fah, ah + (wm * 32 + m * 16) * 72 + k1 * 16, 72);
                wmma::load_matrix_sync(fal, al + (wm * 32 + m * 16) * 72 + k1 * 16, 72);
                wmma::mma_sync(acc[m], fah, fbh, acc[m]);
                wmma::mma_sync(acc[m], fah, fbl, acc[m]);
                wmma::mma_sync(acc[m], fal, fbh, acc[m]);
            }
        }
    }
    __syncthreads();   // operands dead; os overwrites
    #pragma unroll
    for (int m = 0; m < 2; m++)
        wmma::store_matrix_sync(&os[(wm * 32 + m * 16) * 72 + wn * 16], acc[m], 72,
                                wmma::mem_row_major);
    __syncthreads();

    float2 ob = ((const float2*)out_b)[lane];
    float2 g2 = ((const float2*)ln_g)[lane];
    float2 b2 = ((const float2*)ln_b)[lane];
    #pragma unroll
    for (int q = 0; q < 8; q++) {
        int r = warp * 8 + q;
        int node = node0 + r;
        float2 v = *(float2*)&os[r * 72 + lane * 2];
        float x0 = v.x + ob.x;
        float x1 = v.y + ob.y;
        float p = x0 + x1;
        float s = x0 * x0 + x1 * x1;
        #pragma unroll
        for (int o = 16; o > 0; o >>= 1) {
            p += __shfl_xor_sync(0xffffffffu, p, o);
            s += __shfl_xor_sync(0xffffffffu, s, o);
        }
        float mean = p * (1.f / 64.f);
        float var = s * (1.f / 64.f) - mean * mean;
        float rstd = rsqrtf(var + LNEPS);
        if (node < Nn) {
            float2 y;
            y.x = (x0 - mean) * rstd * g2.x + b2.x;
            y.y = (x1 - mean) * rstd * g2.y + b2.y;
            ((float2*)out)[node * 32 + lane] = y;
        }
    }
}

// ---------------- launch ----------------
extern "C" void kernel_launch(void* const* d_in, const int* in_sizes, int n_in,
                              void* d_out, int out_size) {
    const float* h        = (const float*)d_in[0];
    const int*   src      = (const int*)d_in[1];
    const int*   dst      = (const int*)d_in[2];
    const float* fc_w     = (const float*)d_in[3];
    const float* attn_l   = (const float*)d_in[4];
    const float* attn_r   = (const float*)d_in[5];
    const float* gat_bias = (const float*)d_in[6];
    const float* out_w    = (const float*)d_in[7];
    const float* out_b    = (const float*)d_in[8];
    const float* ln_g     = (const float*)d_in[9];
    const float* ln_b     = (const float*)d_in[10];
    float* out = (float*)d_out;

    cudaFuncSetAttribute(k_gemm1, cudaFuncAttributeMaxDynamicSharedMemorySize, 52224);
    cudaFuncSetAttribute(k_gemm2, cudaFuncAttributeMaxDynamicSharedMemorySize, 73728);

    k_hist_split<<<(Ee + 255) / 256, 256>>>(dst, fc_w, out_w);       // 1
    k_scan_part<<<SCAN_BLOCKS, 1024>>>();                            // 2
    k_scan_final2<<<SCAN_BLOCKS, 1024>>>();                          // 3
    k_gemm1<<<(Nn + 63) / 64, 256, 52224>>>(h, attn_l, attn_r);      // 4 (capture slot)
    k_scatterw<<<(Ee + 255) / 256, 256>>>(src, dst);                 // 5
    k_gather<<<(Nn + 7) / 8, 256>>>(gat_bias);                       // 6
    k_gemm2<<<(Nn + 63) / 64, 256, 73728>>>(out_b, ln_g, ln_b, out); // 7
}

// round 7
// speedup vs baseline: 2.9557x; 1.2587x over previous
#include <cuda_runtime.h>
#include <cuda_fp16.h>
#include <cuda_pipeline.h>
#include <mma.h>
#include <math.h>

using namespace nvcuda;

#define Nn 50000
#define Ee 800000
#define NEG 0.2f
#define LNEPS 1e-5f
#define SCAN_BLOCKS ((Nn + 1023) / 1024)   // 49

// ---- scratch (static __device__ arrays: allocation is banned) ----
__device__ __half d_feat_h[Nn * 256];   // GEMM1 output as fp16 [N, H*F]
__device__ float d_el[Nn * 4];
__device__ float d_er[Nn * 4];
__device__ __half d_rst_hi[Nn * 256];   // aggregated features (fp16)
__device__ __half d_w1hi[64 * 256];     // fc_w split
__device__ __half d_w1lo[64 * 256];
__device__ __half d_w2hi[256 * 64];     // out_w split
__device__ __half d_w2lo[256 * 64];
__device__ int   d_cnt[Nn];             // zero-init at load; re-zeroed each call
__device__ int   d_off[Nn + 1];
__device__ int   d_cur[Nn];
__device__ int   d_bsum[SCAN_BLOCKS];
__device__ int   d_esrc[Ee];            // src ids sorted by dst (CSR payload)

// ---- host-side stream/event resources, created once at module init ----
struct GatStreams {
    cudaStream_t s2;
    cudaEvent_t ev_fork, ev_join;
    GatStreams() {
        cudaStreamCreate(&s2);
        cudaEventCreateWithFlags(&ev_fork, cudaEventDisableTiming);
        cudaEventCreateWithFlags(&ev_join, cudaEventDisableTiming);
    }
};
static GatStreams g_gs;

// ---------------- weight pre-split ----------------
__global__ void k_splitw(const float* __restrict__ fc_w, const float* __restrict__ out_w) {
    int i = blockIdx.x * blockDim.x + threadIdx.x;
    if (i < 64 * 256) {
        float f1 = fc_w[i];
        __half h1 = __float2half_rn(f1);
        d_w1hi[i] = h1;
        d_w1lo[i] = __float2half_rn(f1 - __half2float(h1));
        float f2 = out_w[i];
        __half h2 = __float2half_rn(f2);
        d_w2hi[i] = h2;
        d_w2lo[i] = __float2half_rn(f2 - __half2float(h2));
    }
}

// ---------------- CSR build (independent side-stream chain) ----------------
__global__ void k_hist(const int* __restrict__ dst) {
    int i = blockIdx.x * blockDim.x + threadIdx.x;
    if (i < Ee) atomicAdd(&d_cnt[dst[i]], 1);
}

__global__ void k_scan_part() {
    __shared__ int wsum[32];
    int t = threadIdx.x, b = blockIdx.x;
    int lane = t & 31, wid = t >> 5;
    int i = b * 1024 + t;
    int v = (i < Nn) ? d_cnt[i] : 0;
    int x = v;
    #pragma unroll
    for (int o = 1; o < 32; o <<= 1) {
        int y = __shfl_up_sync(0xffffffffu, x, o);
        if (lane >= o) x += y;
    }
    if (lane == 31) wsum[wid] = x;
    __syncthreads();
    if (wid == 0) {
        int s = wsum[lane];
        #pragma unroll
        for (int o = 1; o < 32; o <<= 1) {
            int y = __shfl_up_sync(0xffffffffu, s, o);
            if (lane >= o) s += y;
        }
        wsum[lane] = s;
    }
    __syncthreads();
    int base = wid ? wsum[wid - 1] : 0;
    if (i < Nn) d_off[i] = base + x - v;
    if (t == 0) d_bsum[b] = wsum[31];
}

__global__ void k_scan_final2() {
    __shared__ int sbase;
    int t = threadIdx.x, b = blockIdx.x;
    if (t < 32) {
        int v = 0;
        for (int j = t; j < b; j += 32) v += d_bsum[j];
        #pragma unroll
        for (int o = 16; o > 0; o >>= 1) v += __shfl_xor_sync(0xffffffffu, v, o);
        if (t == 0) sbase = v;
    }
    __syncthreads();
    int i = b * 1024 + t;
    if (i < Nn) {
        int c = d_cnt[i];
        int off = d_off[i] + sbase;
        d_off[i] = off;
        d_cur[i] = off;
        d_cnt[i] = 0;
        if (i == Nn - 1) d_off[Nn] = off + c;
    }
}

__global__ void k_scatter(const int* __restrict__ src, const int* __restrict__ dst) {
    int i = blockIdx.x * blockDim.x + threadIdx.x;
    if (i < Ee) {
        int p = atomicAdd(&d_cur[dst[i]], 1);
        d_esrc[p] = src[i];
    }
}

// ---------------- GEMM1: feat = h @ fc_w, fp16 split MMA (3 products) ----------------
__global__ void k_gemm1(const float* __restrict__ h,
                        const float* __restrict__ attn_l, const float* __restrict__ attn_r) {
    extern __shared__ __align__(128) __half dyn[];
    __half* ah = dyn;                    // 64 x 72
    __half* al = ah + 4608;
    float* os = (float*)dyn;             // 32 x 264 fp32 staging (per phase)
    int t = threadIdx.x;
    int lane = t & 31, warp = t >> 5;
    int node0 = blockIdx.x * 64;

    #pragma unroll
    for (int i = 0; i < 4; i++) {
        int idx = t + i * 256;              // float4 idx; 16 per node
        int row = idx >> 4, c4 = idx & 15;
        float4 v = make_float4(0.f, 0.f, 0.f, 0.f);
        int node = node0 + row;
        if (node < Nn) v = ((const float4*)h)[node * 16 + c4];
        __half h0 = __float2half_rn(v.x), h1 = __float2half_rn(v.y);
        __half h2 = __float2half_rn(v.z), h3 = __float2half_rn(v.w);
        __half2 ph[2] = {__halves2half2(h0, h1), __halves2half2(h2, h3)};
        __half2 pl[2] = {
            __halves2half2(__float2half_rn(v.x - __half2float(h0)),
                           __float2half_rn(v.y - __half2float(h1))),
            __halves2half2(__float2half_rn(v.z - __half2float(h2)),
                           __float2half_rn(v.w - __half2float(h3)))};
        *(uint2*)&ah[row * 72 + c4 * 4] = *(uint2*)ph;
        *(uint2*)&al[row * 72 + c4 * 4] = *(uint2*)pl;
    }

    auto stage_b = [&](int k, int q) {
        __half* bh = dyn + 9216 + q * 8448;
        __half* bl = bh + 4224;
        #pragma unroll
        for (int i = 0; i < 2; i++) {
            int idx = t + i * 256;          // uint4 idx over 16x32
            int row = idx >> 5, c8 = idx & 31;
            __pipeline_memcpy_async(&bh[row * 264 + c8 * 8],
                                    &((const uint4*)d_w1hi)[(k * 16 + row) * 32 + c8], 16);
            __pipeline_memcpy_async(&bl[row * 264 + c8 * 8],
                                    &((const uint4*)d_w1lo)[(k * 16 + row) * 32 + c8], 16);
        }
        __pipeline_commit();
    };
    stage_b(0, 0);

    int wm = warp >> 2, wn = warp & 3;

    wmma::fragment<wmma::matrix_a, 16, 16, 16, __half, wmma::row_major> fah, fal;
    wmma::fragment<wmma::matrix_b, 16, 16, 16, __half, wmma::row_major> fbh, fbl;
    wmma::fragment<wmma::accumulator, 16, 16, 16, float> acc[2][4];
    #pragma unroll
    for (int m = 0; m < 2; m++)
        #pragma unroll
        for (int j = 0; j < 4; j++) wmma::fill_fragment(acc[m][j], 0.f);

    for (int k0 = 0; k0 < 4; k0++) {
        __syncthreads();
        if (k0 < 3) {
            stage_b(k0 + 1, (k0 + 1) & 1);
            __pipeline_wait_prior(1);
        } else {
            __pipeline_wait_prior(0);
        }
        __syncthreads();
        __half* bh = dyn + 9216 + (k0 & 1) * 8448;
        __half* bl = bh + 4224;
        #pragma unroll
        for (int m = 0; m < 2; m++) {
            wmma::load_matrix_sync(fah, ah + (wm * 32 + m * 16) * 72 + k0 * 16, 72);
            wmma::load_matrix_sync(fal, al + (wm * 32 + m * 16) * 72 + k0 * 16, 72);
            #pragma unroll
            for (int j = 0; j < 4; j++) {
                wmma::load_matrix_sync(fbh, bh + wn * 64 + j * 16, 264);
                wmma::load_matrix_sync(fbl, bl + wn * 64 + j * 16, 264);
                wmma::mma_sync(acc[m][j], fah, fbh, acc[m][j]);
                wmma::mma_sync(acc[m][j], fah, fbl, acc[m][j]);
                wmma::mma_sync(acc[m][j], fal, fbh, acc[m][j]);
            }
        }
    }
    __syncthreads();

    float4 al0 = ((const float4*)attn_l)[lane * 2];
    float4 al1 = ((const float4*)attn_l)[lane * 2 + 1];
    float4 ar0 = ((const float4*)attn_r)[lane * 2];
    float4 ar1 = ((const float4*)attn_r)[lane * 2 + 1];

    #pragma unroll
    for (int phase = 0; phase < 2; phase++) {
        if (wm == phase) {
            #pragma unroll
            for (int m = 0; m < 2; m++)
                #pragma unroll
                for (int j = 0; j < 4; j++)
                    wmma::store_matrix_sync(&os[(m * 16) * 264 + wn * 64 + j * 16],
                                            acc[m][j], 264, wmma::mem_row_major);
        }
        __syncthreads();
        #pragma unroll
        for (int q = 0; q < 4; q++) {
            int r = warp * 4 + q;
            int node = node0 + phase * 32 + r;
            float4 v0 = *(float4*)&os[r * 264 + lane * 8];
            float4 v1 = *(float4*)&os[r * 264 + lane * 8 + 4];
            float pl = v0.x * al0.x + v0.y * al0.y + v0.z * al0.z + v0.w * al0.w +
                       v1.x * al1.x + v1.y * al1.y + v1.z * al1.z + v1.w * al1.w;
            float pr = v0.x * ar0.x + v0.y * ar0.y + v0.z * ar0.z + v0.w * ar0.w +
                       v1.x * ar1.x + v1.y * ar1.y + v1.z * ar1.z + v1.w * ar1.w;
            #pragma unroll
            for (int o = 4; o > 0; o >>= 1) {
                pl += __shfl_xor_sync(0xffffffffu, pl, o);
                pr += __shfl_xor_sync(0xffffffffu, pr, o);
            }
            if (node < Nn) {
                __half2 p[4];
                p[0] = __floats2half2_rn(v0.x, v0.y);
                p[1] = __floats2half2_rn(v0.z, v0.w);
                p[2] = __floats2half2_rn(v1.x, v1.y);
                p[3] = __floats2half2_rn(v1.z, v1.w);
                *(uint4*)&d_feat_h[node * 256 + lane * 8] = *(uint4*)p;
                if ((lane & 7) == 0) {
                    int head = lane >> 3;
                    d_el[node * 4 + head] = pl;
                    d_er[node * 4 + head] = pr;
                }
            }
        }
        __syncthreads();
    }
}

// helper: accumulate 8 halves (uint4) scaled by w into a[8]
__device__ __forceinline__ void acc8(float* a, uint4 f, float w) {
    float2 p0 = __half22float2(*(__half2*)&f.x);
    float2 p1 = __half22float2(*(__half2*)&f.y);
    float2 p2 = __half22float2(*(__half2*)&f.z);
    float2 p3 = __half22float2(*(__half2*)&f.w);
    a[0] += w * p0.x; a[1] += w * p0.y;
    a[2] += w * p1.x; a[3] += w * p1.y;
    a[4] += w * p2.x; a[5] += w * p2.y;
    a[6] += w * p3.x; a[7] += w * p3.y;
}

// ---------------- Gather: softmax weight computed in-loop (overlaps L2 latency) ----
// Warp per dst node; lane owns 8 consecutive cols (head = lane>>3).
__global__ void k_gather(const float* __restrict__ gat_bias) {
    int gw = (blockIdx.x * blockDim.x + threadIdx.x) >> 5;
    int lane = threadIdx.x & 31;
    if (gw >= Nn) return;
    int n = gw;
    int head = lane >> 3;

    float er_h = d_er[n * 4 + head];
    int beg = d_off[n], end = d_off[n + 1];
    float s = 0.f;
    float a[8] = {0.f, 0.f, 0.f, 0.f, 0.f, 0.f, 0.f, 0.f};

    int i = beg;
    for (; i + 2 <= end; i += 2) {
        int s0 = d_esrc[i];
        int s1 = d_esrc[i + 1];
        float el0 = d_el[s0 * 4 + head];
        float el1 = d_el[s1 * 4 + head];
        uint4 f0 = *(const uint4*)&d_feat_h[(size_t)s0 * 256 + lane * 8];
        uint4 f1 = *(const uint4*)&d_feat_h[(size_t)s1 * 256 + lane * 8];
        float e0 = el0 + er_h; e0 = e0 > 0.f ? e0 : NEG * e0;
        float e1 = el1 + er_h; e1 = e1 > 0.f ? e1 : NEG * e1;
        // logits small (|e| < ~8): exp cannot overflow; skip max-subtraction
        float w0 = __expf(e0);
        float w1 = __expf(e1);
        s += w0 + w1;
        acc8(a, f0, w0);
        acc8(a, f1, w1);
    }
    if (i < end) {
        int s0 = d_esrc[i];
        float el0 = d_el[s0 * 4 + head];
        uint4 f0 = *(const uint4*)&d_feat_h[(size_t)s0 * 256 + lane * 8];
        float e0 = el0 + er_h; e0 = e0 > 0.f ? e0 : NEG * e0;
        float w0 = __expf(e0);
        s += w0;
        acc8(a, f0, w0);
    }

    float inv = s > 0.f ? 1.f / s : 0.f;
    float4 b0 = ((const float4*)gat_bias)[lane * 2];
    float4 b1 = ((const float4*)gat_bias)[lane * 2 + 1];
    float o[8];
    o[0] = a[0] * inv + b0.x; o[1] = a[1] * inv + b0.y;
    o[2] = a[2] * inv + b0.z; o[3] = a[3] * inv + b0.w;
    o[4] = a[4] * inv + b1.x; o[5] = a[5] * inv + b1.y;
    o[6] = a[6] * inv + b1.z; o[7] = a[7] * inv + b1.w;

    __half2 hi[4];
    #pragma unroll
    for (int j = 0; j < 4; j++)
        hi[j] = __floats2half2_rn(o[2 * j], o[2 * j + 1]);
    *(uint4*)&d_rst_hi[n * 256 + lane * 8] = *(uint4*)hi;
}

// ---------------- GEMM2 + LayerNorm, 2-product fp16 MMA (A-hi only) ----------------
// Dynamic smem: 2 buffers of {ah,bh,bl}[64*72]; fp32 staging aliases.
__global__ void k_gemm2(const float* __restrict__ out_b,
                        const float* __restrict__ ln_g, const float* __restrict__ ln_b,
                        float* __restrict__ out) {
    extern __shared__ __align__(128) __half dyn[];
    float* os = (float*)dyn;          // 64 x 72 fp32 staging
    int t = threadIdx.x;
    int lane = t & 31, warp = t >> 5;
    int node0 = blockIdx.x * 64;

    auto stage_ab = [&](int kc, int q) {
        __half* base = dyn + q * 13824;
        __half* ah = base;
        __half* bh = base + 4608;
        __half* bl = base + 9216;
        #pragma unroll
        for (int i = 0; i < 2; i++) {
            int idx = t + i * 256;          // uint4 idx over 64x8
            int row = idx >> 3, c8 = idx & 7;
            int node = node0 + row;
            int nn = node < Nn ? node : 0;
            size_t zf = node < Nn ? 0 : 16;
            __pipeline_memcpy_async(&ah[row * 72 + c8 * 8],
                                    &((const uint4*)d_rst_hi)[nn * 32 + kc * 8 + c8], 16, zf);
            __pipeline_memcpy_async(&bh[row * 72 + c8 * 8],
                                    &((const uint4*)d_w2hi)[(kc * 64 + row) * 8 + c8], 16);
            __pipeline_memcpy_async(&bl[row * 72 + c8 * 8],
                                    &((const uint4*)d_w2lo)[(kc * 64 + row) * 8 + c8], 16);
        }
        __pipeline_commit();
    };
    stage_ab(0, 0);

    int wm = warp >> 2, wn = warp & 3;

    wmma::fragment<wmma::matrix_a, 16, 16, 16, __half, wmma::row_major> fah;
    wmma::fragment<wmma::matrix_b, 16, 16, 16, __half, wmma::row_major> fbh, fbl;
    wmma::fragment<wmma::accumulator, 16, 16, 16, float> acc[2];
    wmma::fill_fragment(acc[0], 0.f);
    wmma::fill_fragment(acc[1], 0.f);

    for (int kc = 0; kc < 4; kc++) {
        __syncthreads();
        if (kc < 3) {
            stage_ab(kc + 1, (kc + 1) & 1);
            __pipeline_wait_prior(1);
        } else {
            __pipeline_wait_prior(0);
        }
        __syncthreads();
        __half* base = dyn + (kc & 1) * 13824;
        __half* ah = base;
        __half* bh = base + 4608;
        __half* bl = base + 9216;
        #pragma unroll
        for (int k1 = 0; k1 < 4; k1++) {
            wmma::load_matrix_sync(fbh, bh + k1 * 16 * 72 + wn * 16, 72);
            wmma::load_matrix_sync(fbl, bl + k1 * 16 * 72 + wn * 16, 72);
            #pragma unroll
            for (int m = 0; m < 2; m++) {
                wmma::load_matrix_sync(fah, ah + (wm * 32 + m * 16) * 72 + k1 * 16, 72);
                wmma::mma_sync(acc[m], fah, fbh, acc[m]);
                wmma::mma_sync(acc[m], fah, fbl, acc[m]);
            }
        }
    }
    __syncthreads();
    #pragma unroll
    for (int m = 0; m < 2; m++)
        wmma::store_matrix_sync(&os[(wm * 32 + m * 16) * 72 + wn * 16], acc[m], 72,
                                wmma::mem_row_major);
    __syncthreads();

    float2 ob = ((const float2*)out_b)[lane];
    float2 g2 = ((const float2*)ln_g)[lane];
    float2 b2 = ((const float2*)ln_b)[lane];
    #pragma unroll
    for (int q = 0; q < 8; q++) {
        int r = warp * 8 + q;
        int node = node0 + r;
        float2 v = *(float2*)&os[r * 72 + lane * 2];
        float x0 = v.x + ob.x;
        float x1 = v.y + ob.y;
        float p = x0 + x1;
        float s = x0 * x0 + x1 * x1;
        #pragma unroll
        for (int o = 16; o > 0; o >>= 1) {
            p += __shfl_xor_sync(0xffffffffu, p, o);
            s += __shfl_xor_sync(0xffffffffu, s, o);
        }
        float mean = p * (1.f / 64.f);
        float var = s * (1.f / 64.f) - mean * mean;
        float rstd = rsqrtf(var + LNEPS);
        if (node < Nn) {
            float2 y;
            y.x = (x0 - mean) * rstd * g2.x + b2.x;
            y.y = (x1 - mean) * rstd * g2.y + b2.y;
            ((float2*)out)[node * 32 + lane] = y;
        }
    }
}

// ---------------- launch ----------------
extern "C" void kernel_launch(void* const* d_in, const int* in_sizes, int n_in,
                              void* d_out, int out_size) {
    const float* h        = (const float*)d_in[0];
    const int*   src      = (const int*)d_in[1];
    const int*   dst      = (const int*)d_in[2];
    const float* fc_w     = (const float*)d_in[3];
    const float* attn_l   = (const float*)d_in[4];
    const float* attn_r   = (const float*)d_in[5];
    const float* gat_bias = (const float*)d_in[6];
    const float* out_w    = (const float*)d_in[7];
    const float* out_b    = (const float*)d_in[8];
    const float* ln_g     = (const float*)d_in[9];
    const float* ln_b     = (const float*)d_in[10];
    float* out = (float*)d_out;

    cudaFuncSetAttribute(k_gemm1, cudaFuncAttributeMaxDynamicSharedMemorySize, 52224);
    cudaFuncSetAttribute(k_gemm2, cudaFuncAttributeMaxDynamicSharedMemorySize, 55296);

    // fork: CSR chain on side stream, fully independent of the GEMM1 chain
    cudaEventRecord(g_gs.ev_fork, 0);
    cudaStreamWaitEvent(g_gs.s2, g_gs.ev_fork, 0);
    k_hist<<<(Ee + 255) / 256, 256, 0, g_gs.s2>>>(dst);
    k_scan_part<<<SCAN_BLOCKS, 1024, 0, g_gs.s2>>>();
    k_scan_final2<<<SCAN_BLOCKS, 1024, 0, g_gs.s2>>>();
    k_scatter<<<(Ee + 255) / 256, 256, 0, g_gs.s2>>>(src, dst);
    cudaEventRecord(g_gs.ev_join, g_gs.s2);

    // main stream: weights + GEMM1 (concurrent with CSR build)
    k_splitw<<<64, 256>>>(fc_w, out_w);
    k_gemm1<<<(Nn + 63) / 64, 256, 52224>>>(h, attn_l, attn_r);

    // join, then gather + GEMM2
    cudaStreamWaitEvent(0, g_gs.ev_join, 0);
    k_gather<<<(Nn + 7) / 8, 256>>>(gat_bias);
    k_gemm2<<<(Nn + 63) / 64, 256, 55296>>>(out_b, ln_g, ln_b, out);
}